// round 3
// baseline (speedup 1.0000x reference)
#include <cuda_runtime.h>
#include <math.h>

#define BATCH 8
#define H0 512
#define C1 32
#define H1 256
#define H2 128

// -------- scratch (static device globals; no allocation at launch) --------
__device__ float g_pool1[(size_t)BATCH * C1 * H1 * H1];      // 64 MiB
__device__ float g_concat[(size_t)BATCH * 128 * H2 * H2];    // 64 MiB
__device__ float g_mean[BATCH * 128];

// -------- zero the mean accumulator (graph replay must be deterministic) ----
__global__ void zero_mean_kernel() {
    int i = threadIdx.x;
    if (i < BATCH * 128) g_mean[i] = 0.f;
}

// -------- stage 1: conv 3->32 (3x3, pad 1) + relu + maxpool2 ---------------
// grid (16,16, BATCH*32), block (16,16). Writes g_pool1 (B,32,256,256).
__global__ void conv1_kernel(const float* __restrict__ x,
                             const float* __restrict__ w,
                             const float* __restrict__ bias) {
    int oc = blockIdx.z & 31;
    int b  = blockIdx.z >> 5;
    __shared__ float sw[27];
    int tid = threadIdx.y * 16 + threadIdx.x;
    if (tid < 27) sw[tid] = w[oc * 27 + tid];
    __syncthreads();

    int pw = blockIdx.x * 16 + threadIdx.x;   // pooled col 0..255
    int ph = blockIdx.y * 16 + threadIdx.y;   // pooled row
    int r0 = 2 * ph - 1, c0 = 2 * pw - 1;

    const float* xb = x + (size_t)b * 3 * H0 * H0;
    float in[3][4][4];
#pragma unroll
    for (int ic = 0; ic < 3; ic++) {
#pragma unroll
        for (int r = 0; r < 4; r++) {
            int gr = r0 + r;
#pragma unroll
            for (int c = 0; c < 4; c++) {
                int gc = c0 + c;
                in[ic][r][c] = (gr >= 0 && gr < H0 && gc >= 0 && gc < H0)
                               ? xb[(size_t)ic * H0 * H0 + (size_t)gr * H0 + gc] : 0.f;
            }
        }
    }
    float m = -1e30f;
#pragma unroll
    for (int dy = 0; dy < 2; dy++) {
#pragma unroll
        for (int dx = 0; dx < 2; dx++) {
            float acc = 0.f;
#pragma unroll
            for (int ic = 0; ic < 3; ic++)
#pragma unroll
                for (int kh = 0; kh < 3; kh++)
#pragma unroll
                    for (int kw = 0; kw < 3; kw++)
                        acc = fmaf(in[ic][dy + kh][dx + kw], sw[ic * 9 + kh * 3 + kw], acc);
            m = fmaxf(m, acc);
        }
    }
    float v = fmaxf(m + bias[oc], 0.f);
    g_pool1[(((size_t)b * C1 + oc) * H1 + ph) * H1 + pw] = v;
}

// -------- stage 2: conv 32->64 (3x3, pad 1) + relu + maxpool2 --------------
// grid (8,8, BATCH*8), block (16,16). Reads g_pool1; writes g_concat at ch_off.
// Each thread: 8 output channels x 4 conv positions (one pooled output each).
__global__ void conv2_kernel(const float* __restrict__ w,
                             const float* __restrict__ bias,
                             int ch_off) {
    const int TS = 35;                         // odd row stride: no bank conflicts
    __shared__ float tile[34 * TS];
    __shared__ float swt[72];                  // 8 oc x 9 taps for current ic

    int b   = blockIdx.z >> 3;
    int oc0 = (blockIdx.z & 7) * 8;
    int tid = threadIdx.y * 16 + threadIdx.x;
    int ph  = blockIdx.y * 16 + threadIdx.y;   // pooled row 0..127
    int pw  = blockIdx.x * 16 + threadIdx.x;
    int row0 = blockIdx.y * 32 - 1;
    int col0 = blockIdx.x * 32 - 1;

    float acc[8][4];
#pragma unroll
    for (int o = 0; o < 8; o++)
#pragma unroll
        for (int p = 0; p < 4; p++) acc[o][p] = 0.f;

    for (int ic = 0; ic < 32; ic++) {
        const float* src = g_pool1 + ((size_t)b * 32 + ic) * H1 * H1;
        for (int idx = tid; idx < 34 * 34; idx += 256) {
            int r = idx / 34, c = idx - r * 34;
            int gr = row0 + r, gc = col0 + c;
            tile[r * TS + c] = (gr >= 0 && gr < H1 && gc >= 0 && gc < H1)
                               ? src[(size_t)gr * H1 + gc] : 0.f;
        }
        if (tid < 72) swt[tid] = w[(size_t)(oc0 + tid / 9) * 288 + ic * 9 + (tid % 9)];
        __syncthreads();

        float v[4][4];
#pragma unroll
        for (int r = 0; r < 4; r++)
#pragma unroll
            for (int c = 0; c < 4; c++)
                v[r][c] = tile[(2 * threadIdx.y + r) * TS + 2 * threadIdx.x + c];

#pragma unroll
        for (int oc = 0; oc < 8; oc++) {
#pragma unroll
            for (int dy = 0; dy < 2; dy++)
#pragma unroll
                for (int dx = 0; dx < 2; dx++) {
                    float a = acc[oc][dy * 2 + dx];
#pragma unroll
                    for (int kh = 0; kh < 3; kh++)
#pragma unroll
                        for (int kw = 0; kw < 3; kw++)
                            a = fmaf(v[dy + kh][dx + kw], swt[oc * 9 + kh * 3 + kw], a);
                    acc[oc][dy * 2 + dx] = a;
                }
        }
        __syncthreads();
    }

#pragma unroll
    for (int oc = 0; oc < 8; oc++) {
        float m = fmaxf(fmaxf(acc[oc][0], acc[oc][1]), fmaxf(acc[oc][2], acc[oc][3]));
        float v = fmaxf(m + bias[oc0 + oc], 0.f);
        g_concat[(((size_t)b * 128 + ch_off + oc0 + oc) * H2 + ph) * H2 + pw] = v;
    }
}

// -------- fuse: conv 128->128 (3x3, pad 1) + relu + global-mean accumulate --
// grid (8,8, BATCH*16), block (16,16). Reads g_concat; atomicAdd into g_mean.
__global__ void fuse_kernel(const float* __restrict__ w,
                            const float* __restrict__ bias) {
    const int TS = 19;
    __shared__ float swall[8 * 128 * 9];       // all taps for this block's 8 ocs
    __shared__ float tile[18 * TS];

    int b   = blockIdx.z >> 4;
    int oc0 = (blockIdx.z & 15) * 8;
    int tid = threadIdx.y * 16 + threadIdx.x;
    int row0 = blockIdx.y * 16 - 1;
    int col0 = blockIdx.x * 16 - 1;

    for (int i = tid; i < 8 * 128 * 9; i += 256) {
        int oc = i / 1152;
        int rem = i - oc * 1152;               // ic*9 + k
        swall[i] = w[(size_t)(oc0 + oc) * 1152 + rem];
    }

    float acc[8];
#pragma unroll
    for (int o = 0; o < 8; o++) acc[o] = 0.f;

    for (int ic = 0; ic < 128; ic++) {
        const float* src = g_concat + ((size_t)b * 128 + ic) * H2 * H2;
        for (int idx = tid; idx < 18 * 18; idx += 256) {
            int r = idx / 18, c = idx - r * 18;
            int gr = row0 + r, gc = col0 + c;
            tile[r * TS + c] = (gr >= 0 && gr < H2 && gc >= 0 && gc < H2)
                               ? src[(size_t)gr * H2 + gc] : 0.f;
        }
        __syncthreads();                       // also orders swall before first use

        float v[3][3];
#pragma unroll
        for (int r = 0; r < 3; r++)
#pragma unroll
            for (int c = 0; c < 3; c++)
                v[r][c] = tile[(threadIdx.y + r) * TS + threadIdx.x + c];

#pragma unroll
        for (int oc = 0; oc < 8; oc++) {
            float a = acc[oc];
#pragma unroll
            for (int kh = 0; kh < 3; kh++)
#pragma unroll
                for (int kw = 0; kw < 3; kw++)
                    a = fmaf(v[kh][kw], swall[oc * 1152 + ic * 9 + kh * 3 + kw], a);
            acc[oc] = a;
        }
        __syncthreads();
    }

#pragma unroll
    for (int oc = 0; oc < 8; oc++) {
        float r = fmaxf(acc[oc] + bias[oc0 + oc], 0.f);
#pragma unroll
        for (int off = 16; off > 0; off >>= 1)
            r += __shfl_down_sync(0xffffffffu, r, off);
        if ((tid & 31) == 0)
            atomicAdd(&g_mean[b * 128 + oc0 + oc], r);
    }
}

// -------- head: det 1x1 conv + sigmoid + NMS (n=3) + write all outputs -----
// grid (8), block (32). Output layout (f32): p[144] | boxes[96] | scores[24] | keep[24]
__global__ void head_kernel(const float* __restrict__ det_w,
                            const float* __restrict__ det_b,
                            float* __restrict__ out) {
    int b = blockIdx.x;
    int lane = threadIdx.x;
    __shared__ float pv[18];
    if (lane < 18) {
        float acc = det_b[lane];
        for (int c = 0; c < 128; c++)
            acc = fmaf(det_w[lane * 128 + c], g_mean[b * 128 + c] * (1.f / 16384.f), acc);
        pv[lane] = acc;
    }
    __syncthreads();
    if (lane != 0) return;

    // p
    for (int i = 0; i < 18; i++) out[b * 18 + i] = pv[i];

    float bx[3][4], s[3], eff[3];
    bool conf[3];
    for (int a = 0; a < 3; a++) {
        for (int k = 0; k < 4; k++) bx[a][k] = pv[a * 6 + k];
        s[a] = 1.f / (1.f + expf(-pv[a * 6 + 4]));
        conf[a] = s[a] > 0.5f;
        eff[a] = conf[a] ? s[a] : -INFINITY;
    }

    // stable argsort descending (3 elems): strict > keeps lowest index on ties
    int order[3];
    bool used[3] = {false, false, false};
    for (int i = 0; i < 3; i++) {
        int best = -1;
        for (int a = 0; a < 3; a++)
            if (!used[a] && (best < 0 || eff[a] > eff[best])) best = a;
        order[i] = best;
        used[best] = true;
    }

    // ordered boxes + areas
    float ox1[3], oy1[3], ox2[3], oy2[3], area[3];
    for (int i = 0; i < 3; i++) {
        int a = order[i];
        ox1[i] = bx[a][0]; oy1[i] = bx[a][1]; ox2[i] = bx[a][2]; oy2[i] = bx[a][3];
        area[i] = (ox2[i] - ox1[i]) * (oy2[i] - oy1[i]);
    }

    bool keep_s[3], sup[3] = {false, false, false};
    for (int i = 0; i < 3; i++) {
        bool valid = !sup[i];
        keep_s[i] = valid;
        if (valid) {
            for (int j = i + 1; j < 3; j++) {
                float ix1 = fmaxf(ox1[i], ox1[j]);
                float iy1 = fmaxf(oy1[i], oy1[j]);
                float ix2 = fminf(ox2[i], ox2[j]);
                float iy2 = fminf(oy2[i], oy2[j]);
                float inter = fmaxf(ix2 - ix1, 0.f) * fmaxf(iy2 - iy1, 0.f);
                float iou = inter / (area[i] + area[j] - inter);
                if (iou > 0.5f) sup[j] = true;
            }
        }
    }
    bool keep[3];
    for (int i = 0; i < 3; i++) keep[order[i]] = keep_s[i];
    for (int a = 0; a < 3; a++) keep[a] = keep[a] && conf[a];

    for (int a = 0; a < 3; a++) {
        for (int k = 0; k < 4; k++) out[144 + b * 12 + a * 4 + k] = bx[a][k];
        out[240 + b * 3 + a] = s[a];
        out[264 + b * 3 + a] = keep[a] ? 1.f : 0.f;
    }
}

// ---------------------------------------------------------------------------
extern "C" void kernel_launch(void* const* d_in, const int* in_sizes, int n_in,
                              void* d_out, int out_size) {
    const float* x      = (const float*)d_in[0];
    const float* rgb_w1 = (const float*)d_in[1];
    const float* rgb_b1 = (const float*)d_in[2];
    const float* rgb_w2 = (const float*)d_in[3];
    const float* rgb_b2 = (const float*)d_in[4];
    const float* ir_w1  = (const float*)d_in[5];
    const float* ir_b1  = (const float*)d_in[6];
    const float* ir_w2  = (const float*)d_in[7];
    const float* ir_b2  = (const float*)d_in[8];
    const float* fuse_w = (const float*)d_in[9];
    const float* fuse_b = (const float*)d_in[10];
    const float* det_w  = (const float*)d_in[11];
    const float* det_b  = (const float*)d_in[12];
    float* out = (float*)d_out;

    dim3 blk(16, 16);

    zero_mean_kernel<<<1, 1024>>>();

    // RGB stream
    conv1_kernel<<<dim3(16, 16, BATCH * 32), blk>>>(x, rgb_w1, rgb_b1);
    conv2_kernel<<<dim3(8, 8, BATCH * 8), blk>>>(rgb_w2, rgb_b2, 0);

    // IR stream (overwrites g_pool1)
    conv1_kernel<<<dim3(16, 16, BATCH * 32), blk>>>(x, ir_w1, ir_b1);
    conv2_kernel<<<dim3(8, 8, BATCH * 8), blk>>>(ir_w2, ir_b2, 64);

    // fuse + global mean
    fuse_kernel<<<dim3(8, 8, BATCH * 16), blk>>>(fuse_w, fuse_b);

    // head + NMS + all outputs
    head_kernel<<<8, 32>>>(det_w, det_b, out);
}

// round 8
// speedup vs baseline: 2.0923x; 2.0923x over previous
#include <cuda_runtime.h>
#include <cuda_bf16.h>
#include <stdint.h>
#include <math.h>

#define BATCH 8
#define H0 512
#define H1 256
#define H2 128

// ------------------------- scratch globals (no allocs) ---------------------
__device__ float g_pool1a[(size_t)BATCH * 32 * H1 * H1];
__device__ float g_pool1b[(size_t)BATCH * 32 * H1 * H1];
__device__ float g_concat[(size_t)BATCH * 128 * H2 * H2];
__device__ float g_mean[BATCH * 128];

// pre-packed bf16 weights, K-major uint32 pairs: [hi/lo][...][oc][kk_pair]
__device__ uint32_t g_wc1[2][64][16];          // conv1: both streams, K=32
__device__ uint32_t g_wc2[2][18][64][16];      // conv2: [stream*9+tap], K=32
__device__ uint32_t g_wf[2][9][128][64];       // fuse:  [tap], K=128

// ------------------------- numeric helpers ---------------------------------
__device__ __forceinline__ unsigned short bf_hi(float v) {
    return __bfloat16_as_ushort(__float2bfloat16(v));
}
__device__ __forceinline__ unsigned short bf_lo(float v) {
    float h = __bfloat162float(__float2bfloat16(v));
    return __bfloat16_as_ushort(__float2bfloat16(v - h));
}
__device__ __forceinline__ uint32_t pack_hi2(float v0, float v1) {
    return (uint32_t)bf_hi(v0) | ((uint32_t)bf_hi(v1) << 16);
}
__device__ __forceinline__ uint32_t pack_lo2(float v0, float v1) {
    return (uint32_t)bf_lo(v0) | ((uint32_t)bf_lo(v1) << 16);
}

// m16n8k16 bf16 HMMA, D += A*B (fp32 accumulate)
__device__ __forceinline__ void mma16816(float* d, const uint32_t* a, const uint32_t* b) {
    asm volatile(
        "mma.sync.aligned.m16n8k16.row.col.f32.bf16.bf16.f32 "
        "{%0,%1,%2,%3}, {%4,%5,%6,%7}, {%8,%9}, {%0,%1,%2,%3};"
        : "+f"(d[0]), "+f"(d[1]), "+f"(d[2]), "+f"(d[3])
        : "r"(a[0]), "r"(a[1]), "r"(a[2]), "r"(a[3]), "r"(b[0]), "r"(b[1]));
}

// Build hi/lo A fragments from 8 fp32 values (rows r0,r1 x cols c,c+1,c+8,c+9)
__device__ __forceinline__ void build_a(uint32_t* aHi, uint32_t* aLo,
                                        float v00, float v01, float v08, float v09,
                                        float v10, float v11, float v18, float v19) {
    aHi[0] = pack_hi2(v00, v01); aLo[0] = pack_lo2(v00, v01);
    aHi[1] = pack_hi2(v10, v11); aLo[1] = pack_lo2(v10, v11);
    aHi[2] = pack_hi2(v08, v09); aLo[2] = pack_lo2(v08, v09);
    aHi[3] = pack_hi2(v18, v19); aLo[3] = pack_lo2(v18, v19);
}

// ------------------------- misc small kernels ------------------------------
__global__ void zero_mean_kernel() {
    int i = threadIdx.x;
    if (i < BATCH * 128) g_mean[i] = 0.f;
}

// ------------------------- weight transforms -------------------------------
__global__ void xform_w1(const float* __restrict__ wr, const float* __restrict__ wi) {
    int idx = blockIdx.x * 256 + threadIdx.x;       // 64 oc x 16 pairs
    if (idx >= 64 * 16) return;
    int oc = idx >> 4;
    int p = idx & 15;
    const float* w = (oc < 32) ? wr : wi;
    int ocl = oc & 31;
    float v0 = 0.f, v1 = 0.f;
    int kk0 = 2 * p, kk1 = 2 * p + 1;
    if (kk0 < 27) v0 = w[ocl * 27 + (kk0 % 3) * 9 + (kk0 / 3)];
    if (kk1 < 27) v1 = w[ocl * 27 + (kk1 % 3) * 9 + (kk1 / 3)];
    g_wc1[0][oc][p] = pack_hi2(v0, v1);
    g_wc1[1][oc][p] = pack_lo2(v0, v1);
}

__global__ void xform_w2(const float* __restrict__ w, int sidx) {
    int idx = blockIdx.x * 256 + threadIdx.x;       // 9 tap x 64 oc x 16 pairs
    if (idx >= 9 * 64 * 16) return;
    int tap = idx >> 10;
    int r = idx & 1023;
    int oc = r >> 4;
    int p = r & 15;
    float v0 = w[oc * 288 + (2 * p) * 9 + tap];
    float v1 = w[oc * 288 + (2 * p + 1) * 9 + tap];
    g_wc2[0][sidx * 9 + tap][oc][p] = pack_hi2(v0, v1);
    g_wc2[1][sidx * 9 + tap][oc][p] = pack_lo2(v0, v1);
}

__global__ void xform_wf(const float* __restrict__ w) {
    int idx = blockIdx.x * 256 + threadIdx.x;       // 9 tap x 128 oc x 64 pairs
    if (idx >= 9 * 128 * 64) return;
    int tap = idx >> 13;
    int r = idx & 8191;
    int oc = r >> 6;
    int p = r & 63;
    float v0 = w[(oc * 128 + 2 * p) * 9 + tap];
    float v1 = w[(oc * 128 + 2 * p + 1) * 9 + tap];
    g_wf[0][tap][oc][p] = pack_hi2(v0, v1);
    g_wf[1][tap][oc][p] = pack_lo2(v0, v1);
}

// ======================= conv1 (both streams in one GEMM) ==================
__device__ __forceinline__ float conv1_fetch(const float* xb, int kk, int py, int px) {
    if (kk >= 27) return 0.f;
    int tap = kk / 3;
    int ic = kk - tap * 3;
    int kh = tap / 3;
    int kw = tap - kh * 3;
    int gy = py + kh - 1;
    int gx = px + kw - 1;
    if (gy < 0 || gy >= H0 || gx < 0 || gx >= H0) return 0.f;
    return xb[(size_t)ic * H0 * H0 + (size_t)gy * H0 + gx];
}

// grid 16384: (b, pooled row Y 0..255, x-group of 64 pre-pool cols).
// M=128 (2 dy x 64 xx), N=64 (32 rgb + 32 ir oc), K=32 (27 used).
__global__ void __launch_bounds__(256, 1)
conv1_mma(const float* __restrict__ x,
          const float* __restrict__ b_rgb,
          const float* __restrict__ b_ir) {
    __shared__ float s[128 * 65];
    int tid = threadIdx.x;
    int wid = tid >> 5;
    int lane = tid & 31;
    int bid = blockIdx.x;
    int x0 = (bid & 7) * 64;
    int Y = (bid >> 3) & 255;
    int b = bid >> 11;
    const float* xb = x + (size_t)b * 3 * H0 * H0;

    int r0 = wid * 16 + (lane >> 2);
    int r1 = r0 + 8;
    int cbase = (lane & 3) * 2;
    int py0 = 2 * Y + (r0 >> 6), px0 = x0 + (r0 & 63);
    int py1 = 2 * Y + (r1 >> 6), px1 = x0 + (r1 & 63);

    float d[8][4];
#pragma unroll
    for (int nb = 0; nb < 8; nb++)
#pragma unroll
        for (int i = 0; i < 4; i++) d[nb][i] = 0.f;

#pragma unroll
    for (int sk = 0; sk < 2; sk++) {
        int k0 = sk * 16 + cbase;
        float v00 = conv1_fetch(xb, k0,     py0, px0);
        float v01 = conv1_fetch(xb, k0 + 1, py0, px0);
        float v08 = conv1_fetch(xb, k0 + 8, py0, px0);
        float v09 = conv1_fetch(xb, k0 + 9, py0, px0);
        float v10 = conv1_fetch(xb, k0,     py1, px1);
        float v11 = conv1_fetch(xb, k0 + 1, py1, px1);
        float v18 = conv1_fetch(xb, k0 + 8, py1, px1);
        float v19 = conv1_fetch(xb, k0 + 9, py1, px1);
        uint32_t aHi[4], aLo[4];
        build_a(aHi, aLo, v00, v01, v08, v09, v10, v11, v18, v19);
        int p0 = (lane & 3) + 8 * sk;
#pragma unroll
        for (int nb = 0; nb < 8; nb++) {
            int n = nb * 8 + (lane >> 2);
            uint32_t bh[2] = { g_wc1[0][n][p0], g_wc1[0][n][p0 + 4] };
            uint32_t bl[2] = { g_wc1[1][n][p0], g_wc1[1][n][p0 + 4] };
            mma16816(d[nb], aHi, bh);
            mma16816(d[nb], aHi, bl);
            mma16816(d[nb], aLo, bh);
        }
    }

#pragma unroll
    for (int nb = 0; nb < 8; nb++) {
        int c = nb * 8 + cbase;
        s[r0 * 65 + c]     = d[nb][0];
        s[r0 * 65 + c + 1] = d[nb][1];
        s[r1 * 65 + c]     = d[nb][2];
        s[r1 * 65 + c + 1] = d[nb][3];
    }
    __syncthreads();
#pragma unroll
    for (int k = 0; k < 8; k++) {
        int oi = tid + k * 256;
        int oc = oi >> 5;
        int j = oi & 31;
        float m0 = fmaxf(s[(2 * j) * 65 + oc], s[(2 * j + 1) * 65 + oc]);
        float m1 = fmaxf(s[(64 + 2 * j) * 65 + oc], s[(64 + 2 * j + 1) * 65 + oc]);
        float bi = (oc < 32) ? b_rgb[oc] : b_ir[oc - 32];
        float v = fmaxf(fmaxf(m0, m1) + bi, 0.f);
        if (oc < 32) {
            g_pool1a[(((size_t)b * 32 + oc) * H1 + Y) * H1 + (x0 >> 1) + j] = v;
        } else {
            g_pool1b[(((size_t)b * 32 + (oc - 32)) * H1 + Y) * H1 + (x0 >> 1) + j] = v;
        }
    }
}

// ======================= conv2 (per stream) ================================
// grid 4096: (b, pooled row Y 0..127, x-group of 64 pre-pool cols).
// M=128, N=64 oc, K = 9 taps x 32 ic.
// which: 0 = rgb (reads g_pool1a), 1 = ir (reads g_pool1b). Selector resolves
// the __device__ global INSIDE device code (host-side symbol address is UB
// and on GB300/ATS silently reads host shadow memory).
__global__ void __launch_bounds__(256, 1)
conv2_mma(int which, const float* __restrict__ bias) {
    __shared__ float s[128 * 65];
    int tid = threadIdx.x;
    int wid = tid >> 5;
    int lane = tid & 31;
    int bid = blockIdx.x;
    int x0 = (bid & 3) * 64;
    int Y = (bid >> 2) & 127;
    int b = bid >> 9;
    const float* src = (which == 0) ? g_pool1a : g_pool1b;
    int wmat0 = which * 9;
    int ch_off = which * 64;
    const float* base = src + (size_t)b * 32 * H1 * H1;
    const size_t PL = (size_t)H1 * H1;

    int r0 = wid * 16 + (lane >> 2);
    int r1 = r0 + 8;
    int cbase = (lane & 3) * 2;

    float d[8][4];
#pragma unroll
    for (int nb = 0; nb < 8; nb++)
#pragma unroll
        for (int i = 0; i < 4; i++) d[nb][i] = 0.f;

    for (int t = 0; t < 9; t++) {
        int kh = t / 3;
        int kw = t - kh * 3;
        int gy0 = 2 * Y + (r0 >> 6) + kh - 1;
        int gx0 = x0 + (r0 & 63) + kw - 1;
        int gy1 = 2 * Y + (r1 >> 6) + kh - 1;
        int gx1 = x0 + (r1 & 63) + kw - 1;
        bool ok0 = (gy0 >= 0 && gy0 < H1 && gx0 >= 0 && gx0 < H1);
        bool ok1 = (gy1 >= 0 && gy1 < H1 && gx1 >= 0 && gx1 < H1);
        const float* q0 = base + (size_t)gy0 * H1 + gx0;
        const float* q1 = base + (size_t)gy1 * H1 + gx1;
        const uint32_t(*wh)[16] = g_wc2[0][wmat0 + t];
        const uint32_t(*wl)[16] = g_wc2[1][wmat0 + t];
#pragma unroll
        for (int sk = 0; sk < 2; sk++) {
            int ic = sk * 16 + cbase;
            float v00 = ok0 ? q0[(size_t)ic * PL] : 0.f;
            float v01 = ok0 ? q0[(size_t)(ic + 1) * PL] : 0.f;
            float v08 = ok0 ? q0[(size_t)(ic + 8) * PL] : 0.f;
            float v09 = ok0 ? q0[(size_t)(ic + 9) * PL] : 0.f;
            float v10 = ok1 ? q1[(size_t)ic * PL] : 0.f;
            float v11 = ok1 ? q1[(size_t)(ic + 1) * PL] : 0.f;
            float v18 = ok1 ? q1[(size_t)(ic + 8) * PL] : 0.f;
            float v19 = ok1 ? q1[(size_t)(ic + 9) * PL] : 0.f;
            uint32_t aHi[4], aLo[4];
            build_a(aHi, aLo, v00, v01, v08, v09, v10, v11, v18, v19);
            int p0 = (lane & 3) + 8 * sk;
#pragma unroll
            for (int nb = 0; nb < 8; nb++) {
                int n = nb * 8 + (lane >> 2);
                uint32_t bh[2] = { wh[n][p0], wh[n][p0 + 4] };
                uint32_t bl[2] = { wl[n][p0], wl[n][p0 + 4] };
                mma16816(d[nb], aHi, bh);
                mma16816(d[nb], aHi, bl);
                mma16816(d[nb], aLo, bh);
            }
        }
    }

#pragma unroll
    for (int nb = 0; nb < 8; nb++) {
        int c = nb * 8 + cbase;
        s[r0 * 65 + c]     = d[nb][0];
        s[r0 * 65 + c + 1] = d[nb][1];
        s[r1 * 65 + c]     = d[nb][2];
        s[r1 * 65 + c + 1] = d[nb][3];
    }
    __syncthreads();
#pragma unroll
    for (int k = 0; k < 8; k++) {
        int oi = tid + k * 256;
        int oc = oi >> 5;
        int j = oi & 31;
        float m0 = fmaxf(s[(2 * j) * 65 + oc], s[(2 * j + 1) * 65 + oc]);
        float m1 = fmaxf(s[(64 + 2 * j) * 65 + oc], s[(64 + 2 * j + 1) * 65 + oc]);
        float v = fmaxf(fmaxf(m0, m1) + bias[oc], 0.f);
        g_concat[(((size_t)b * 128 + ch_off + oc) * H2 + Y) * H2 + (x0 >> 1) + j] = v;
    }
}

// ======================= fuse (128->128 conv + relu + mean) ================
// grid 2048: (b, row y, oc-half). M=128 x-positions, N=64 oc, K = 9 x 128 ic.
__global__ void __launch_bounds__(256, 1)
fuse_mma(const float* __restrict__ bias) {
    __shared__ float s[128 * 65];
    int tid = threadIdx.x;
    int wid = tid >> 5;
    int lane = tid & 31;
    int bid = blockIdx.x;
    int nh = bid & 1;
    int y = (bid >> 1) & 127;
    int b = bid >> 8;
    const float* base = g_concat + (size_t)b * 128 * H2 * H2;
    const size_t PL = (size_t)H2 * H2;

    int r0 = wid * 16 + (lane >> 2);
    int r1 = r0 + 8;
    int cbase = (lane & 3) * 2;

    float d[8][4];
#pragma unroll
    for (int nb = 0; nb < 8; nb++)
#pragma unroll
        for (int i = 0; i < 4; i++) d[nb][i] = 0.f;

    for (int t = 0; t < 9; t++) {
        int kh = t / 3;
        int kw = t - kh * 3;
        int gy = y + kh - 1;
        int gx0 = r0 + kw - 1;
        int gx1 = r1 + kw - 1;
        bool okY = (gy >= 0 && gy < H2);
        bool ok0 = okY && (gx0 >= 0 && gx0 < H2);
        bool ok1 = okY && (gx1 >= 0 && gx1 < H2);
        const float* q0 = base + (size_t)gy * H2 + gx0;
        const float* q1 = base + (size_t)gy * H2 + gx1;
        const uint32_t(*wh)[64] = g_wf[0][t];
        const uint32_t(*wl)[64] = g_wf[1][t];
#pragma unroll
        for (int sk = 0; sk < 8; sk++) {
            int ic = sk * 16 + cbase;
            float v00 = ok0 ? q0[(size_t)ic * PL] : 0.f;
            float v01 = ok0 ? q0[(size_t)(ic + 1) * PL] : 0.f;
            float v08 = ok0 ? q0[(size_t)(ic + 8) * PL] : 0.f;
            float v09 = ok0 ? q0[(size_t)(ic + 9) * PL] : 0.f;
            float v10 = ok1 ? q1[(size_t)ic * PL] : 0.f;
            float v11 = ok1 ? q1[(size_t)(ic + 1) * PL] : 0.f;
            float v18 = ok1 ? q1[(size_t)(ic + 8) * PL] : 0.f;
            float v19 = ok1 ? q1[(size_t)(ic + 9) * PL] : 0.f;
            uint32_t aHi[4], aLo[4];
            build_a(aHi, aLo, v00, v01, v08, v09, v10, v11, v18, v19);
            int p0 = (lane & 3) + 8 * sk;
#pragma unroll
            for (int nb = 0; nb < 8; nb++) {
                int n = nh * 64 + nb * 8 + (lane >> 2);
                uint32_t bh[2] = { wh[n][p0], wh[n][p0 + 4] };
                uint32_t bl[2] = { wl[n][p0], wl[n][p0 + 4] };
                mma16816(d[nb], aHi, bh);
                mma16816(d[nb], aHi, bl);
                mma16816(d[nb], aLo, bh);
            }
        }
    }

#pragma unroll
    for (int nb = 0; nb < 8; nb++) {
        int c = nb * 8 + cbase;
        float b0 = bias[nh * 64 + c];
        float b1 = bias[nh * 64 + c + 1];
        s[r0 * 65 + c]     = fmaxf(d[nb][0] + b0, 0.f);
        s[r0 * 65 + c + 1] = fmaxf(d[nb][1] + b1, 0.f);
        s[r1 * 65 + c]     = fmaxf(d[nb][2] + b0, 0.f);
        s[r1 * 65 + c + 1] = fmaxf(d[nb][3] + b1, 0.f);
    }
    __syncthreads();
    if (tid < 128) {
        int col = tid & 63;
        int rh = tid >> 6;
        float sum = 0.f;
        for (int r = rh * 64; r < rh * 64 + 64; r++) sum += s[r * 65 + col];
        atomicAdd(&g_mean[b * 128 + nh * 64 + col], sum);
    }
}

// ======================= head: det 1x1 + sigmoid + NMS =====================
__global__ void head_kernel(const float* __restrict__ det_w,
                            const float* __restrict__ det_b,
                            float* __restrict__ out) {
    int b = blockIdx.x;
    int lane = threadIdx.x;
    __shared__ float pv[18];
    if (lane < 18) {
        float acc = det_b[lane];
        for (int c = 0; c < 128; c++)
            acc = fmaf(det_w[lane * 128 + c], g_mean[b * 128 + c] * (1.f / 16384.f), acc);
        pv[lane] = acc;
    }
    __syncthreads();
    if (lane != 0) return;

    for (int i = 0; i < 18; i++) out[b * 18 + i] = pv[i];

    float bx[3][4], sc[3], eff[3];
    bool conf[3];
    for (int a = 0; a < 3; a++) {
        for (int k = 0; k < 4; k++) bx[a][k] = pv[a * 6 + k];
        sc[a] = 1.f / (1.f + expf(-pv[a * 6 + 4]));
        conf[a] = sc[a] > 0.5f;
        eff[a] = conf[a] ? sc[a] : -INFINITY;
    }
    int order[3];
    bool used[3] = {false, false, false};
    for (int i = 0; i < 3; i++) {
        int best = -1;
        for (int a = 0; a < 3; a++)
            if (!used[a] && (best < 0 || eff[a] > eff[best])) best = a;
        order[i] = best;
        used[best] = true;
    }
    float ox1[3], oy1[3], ox2[3], oy2[3], area[3];
    for (int i = 0; i < 3; i++) {
        int a = order[i];
        ox1[i] = bx[a][0]; oy1[i] = bx[a][1]; ox2[i] = bx[a][2]; oy2[i] = bx[a][3];
        area[i] = (ox2[i] - ox1[i]) * (oy2[i] - oy1[i]);
    }
    bool keep_s[3];
    bool sup[3] = {false, false, false};
    for (int i = 0; i < 3; i++) {
        bool valid = !sup[i];
        keep_s[i] = valid;
        if (valid) {
            for (int j = i + 1; j < 3; j++) {
                float ix1 = fmaxf(ox1[i], ox1[j]);
                float iy1 = fmaxf(oy1[i], oy1[j]);
                float ix2 = fminf(ox2[i], ox2[j]);
                float iy2 = fminf(oy2[i], oy2[j]);
                float inter = fmaxf(ix2 - ix1, 0.f) * fmaxf(iy2 - iy1, 0.f);
                float iou = inter / (area[i] + area[j] - inter);
                if (iou > 0.5f) sup[j] = true;
            }
        }
    }
    bool kp[3];
    for (int i = 0; i < 3; i++) kp[order[i]] = keep_s[i];
    for (int a = 0; a < 3; a++) kp[a] = kp[a] && conf[a];

    for (int a = 0; a < 3; a++) {
        for (int k = 0; k < 4; k++) out[144 + b * 12 + a * 4 + k] = bx[a][k];
        out[240 + b * 3 + a] = sc[a];
        out[264 + b * 3 + a] = kp[a] ? 1.f : 0.f;
    }
}

// ===========================================================================
extern "C" void kernel_launch(void* const* d_in, const int* in_sizes, int n_in,
                              void* d_out, int out_size) {
    const float* x      = (const float*)d_in[0];
    const float* rgb_w1 = (const float*)d_in[1];
    const float* rgb_b1 = (const float*)d_in[2];
    const float* rgb_w2 = (const float*)d_in[3];
    const float* rgb_b2 = (const float*)d_in[4];
    const float* ir_w1  = (const float*)d_in[5];
    const float* ir_b1  = (const float*)d_in[6];
    const float* ir_w2  = (const float*)d_in[7];
    const float* ir_b2  = (const float*)d_in[8];
    const float* fuse_w = (const float*)d_in[9];
    const float* fuse_b = (const float*)d_in[10];
    const float* det_w  = (const float*)d_in[11];
    const float* det_b  = (const float*)d_in[12];
    float* out = (float*)d_out;

    zero_mean_kernel<<<1, 1024>>>();
    xform_w1<<<4, 256>>>(rgb_w1, ir_w1);
    xform_w2<<<36, 256>>>(rgb_w2, 0);
    xform_w2<<<36, 256>>>(ir_w2, 1);
    xform_wf<<<288, 256>>>(fuse_w);

    conv1_mma<<<16384, 256>>>(x, rgb_b1, ir_b1);
    conv2_mma<<<4096, 256>>>(0, rgb_b2);
    conv2_mma<<<4096, 256>>>(1, ir_b2);
    fuse_mma<<<2048, 256>>>(fuse_b);
    head_kernel<<<8, 32>>>(det_w, det_b, out);
}

// round 9
// speedup vs baseline: 3.9153x; 1.8713x over previous
#include <cuda_runtime.h>
#include <cuda_bf16.h>
#include <stdint.h>
#include <math.h>

#define BATCH 8
#define H0 512
#define H1 256
#define H2 128

typedef unsigned short u16;

// ------------------------- scratch globals (no allocs) ---------------------
// pool1 (per stream) channel-last bf16 hi/lo: [b][y256][x256][c32]
#define NP1 ((size_t)BATCH * 256 * 256 * 32)
__device__ u16 g_p1h[2][NP1];
__device__ u16 g_p1l[2][NP1];
// concat channel-last bf16 hi/lo: [b][y128][x128][c128]
#define NCC ((size_t)BATCH * 128 * 128 * 128)
__device__ u16 g_cch[NCC];
__device__ u16 g_ccl[NCC];
__device__ float g_mean[BATCH * 128];

// pre-packed bf16 weights as uint2 {pair(p0), pair(p0+4)}: [hi/lo][...][oc][sk][t]
__device__ uint2 g_wc1[2][64][2][4];
__device__ uint2 g_wc2[2][18][64][2][4];
__device__ uint2 g_wf[2][9][128][8][4];

// ------------------------- numeric helpers ---------------------------------
__device__ __forceinline__ u16 bf_hi(float v) {
    return __bfloat16_as_ushort(__float2bfloat16(v));
}
__device__ __forceinline__ u16 bf_lo(float v) {
    float h = __bfloat162float(__float2bfloat16(v));
    return __bfloat16_as_ushort(__float2bfloat16(v - h));
}
__device__ __forceinline__ uint32_t pack_hi2(float v0, float v1) {
    return (uint32_t)bf_hi(v0) | ((uint32_t)bf_hi(v1) << 16);
}
__device__ __forceinline__ uint32_t pack_lo2(float v0, float v1) {
    return (uint32_t)bf_lo(v0) | ((uint32_t)bf_lo(v1) << 16);
}

// m16n8k16 bf16 HMMA, D += A*B (fp32 accumulate)
__device__ __forceinline__ void mma16816(float* d, const uint32_t* a, uint32_t b0, uint32_t b1) {
    asm volatile(
        "mma.sync.aligned.m16n8k16.row.col.f32.bf16.bf16.f32 "
        "{%0,%1,%2,%3}, {%4,%5,%6,%7}, {%8,%9}, {%0,%1,%2,%3};"
        : "+f"(d[0]), "+f"(d[1]), "+f"(d[2]), "+f"(d[3])
        : "r"(a[0]), "r"(a[1]), "r"(a[2]), "r"(a[3]), "r"(b0), "r"(b1));
}

// predicated aligned u32 load of two adjacent bf16 channels
__device__ __forceinline__ uint32_t ldp(const u16* p, bool ok, size_t i) {
    return ok ? *(const uint32_t*)(p + i) : 0u;
}

// ------------------------- misc small kernels ------------------------------
__global__ void zero_mean_kernel() {
    int i = threadIdx.x;
    if (i < BATCH * 128) g_mean[i] = 0.f;
}

// ------------------------- weight transforms -------------------------------
__device__ __forceinline__ float w1elem(const float* w, int ocl, int kk) {
    if (kk >= 27) return 0.f;
    int tap = kk / 3;
    int ic = kk - 3 * tap;
    return w[ocl * 27 + ic * 9 + tap];
}

__global__ void xform_w1(const float* __restrict__ wr, const float* __restrict__ wi) {
    int idx = blockIdx.x * 256 + threadIdx.x;       // 64 oc x 2 sk x 4 t
    if (idx >= 512) return;
    int oc = idx >> 3, sk = (idx >> 2) & 1, t = idx & 3;
    const float* w = (oc < 32) ? wr : wi;
    int ocl = oc & 31;
    int pA = t + 8 * sk, pB = pA + 4;
    float a0 = w1elem(w, ocl, 2 * pA), a1 = w1elem(w, ocl, 2 * pA + 1);
    float b0 = w1elem(w, ocl, 2 * pB), b1 = w1elem(w, ocl, 2 * pB + 1);
    g_wc1[0][oc][sk][t] = make_uint2(pack_hi2(a0, a1), pack_hi2(b0, b1));
    g_wc1[1][oc][sk][t] = make_uint2(pack_lo2(a0, a1), pack_lo2(b0, b1));
}

__global__ void xform_w2(const float* __restrict__ w, int sidx) {
    int idx = blockIdx.x * 256 + threadIdx.x;       // 9 tap x 64 oc x 2 sk x 4 t
    if (idx >= 9 * 512) return;
    int tap = idx / 512;
    int rem = idx & 511;
    int oc = rem >> 3, sk = (rem >> 2) & 1, t = rem & 3;
    int pA = t + 8 * sk, pB = pA + 4;
    float a0 = w[oc * 288 + (2 * pA) * 9 + tap],     a1 = w[oc * 288 + (2 * pA + 1) * 9 + tap];
    float b0 = w[oc * 288 + (2 * pB) * 9 + tap],     b1 = w[oc * 288 + (2 * pB + 1) * 9 + tap];
    int mi = sidx * 9 + tap;
    g_wc2[0][mi][oc][sk][t] = make_uint2(pack_hi2(a0, a1), pack_hi2(b0, b1));
    g_wc2[1][mi][oc][sk][t] = make_uint2(pack_lo2(a0, a1), pack_lo2(b0, b1));
}

__global__ void xform_wf(const float* __restrict__ w) {
    int idx = blockIdx.x * 256 + threadIdx.x;       // 9 tap x 128 oc x 8 sk x 4 t
    if (idx >= 9 * 4096) return;
    int tap = idx >> 12;
    int rem = idx & 4095;
    int oc = rem >> 5, sk = (rem >> 2) & 7, t = rem & 3;
    int pA = t + 8 * sk, pB = pA + 4;
    float a0 = w[(oc * 128 + 2 * pA) * 9 + tap],     a1 = w[(oc * 128 + 2 * pA + 1) * 9 + tap];
    float b0 = w[(oc * 128 + 2 * pB) * 9 + tap],     b1 = w[(oc * 128 + 2 * pB + 1) * 9 + tap];
    g_wf[0][tap][oc][sk][t] = make_uint2(pack_hi2(a0, a1), pack_hi2(b0, b1));
    g_wf[1][tap][oc][sk][t] = make_uint2(pack_lo2(a0, a1), pack_lo2(b0, b1));
}

// ======================= conv1 (both streams in one GEMM) ==================
__device__ __forceinline__ float conv1_fetch(const float* xb, int kk, int py, int px) {
    if (kk >= 27) return 0.f;
    int tap = kk / 3;
    int ic = kk - tap * 3;
    int kh = tap / 3;
    int kw = tap - kh * 3;
    int gy = py + kh - 1;
    int gx = px + kw - 1;
    if (gy < 0 || gy >= H0 || gx < 0 || gx >= H0) return 0.f;
    return xb[(size_t)ic * H0 * H0 + (size_t)gy * H0 + gx];
}

// grid 8192: (b, pooled row Y 0..255, x-group of 128 pre-pool cols).
// M=256 (2 dy frags x 128 xx), N=64, K=32 (27 used).
__global__ void __launch_bounds__(256, 1)
conv1_mma(const float* __restrict__ x,
          const float* __restrict__ b_rgb,
          const float* __restrict__ b_ir) {
    __shared__ float s[128 * 65];
    int tid = threadIdx.x;
    int wid = tid >> 5;
    int lane = tid & 31;
    int g = lane >> 2;
    int t = lane & 3;
    int cbase = 2 * t;
    int bid = blockIdx.x;
    int x0 = (bid & 3) * 128;
    int Y = (bid >> 2) & 255;
    int b = bid >> 10;
    const float* xb = x + (size_t)b * 3 * H0 * H0;

    int xx0 = wid * 16 + g;
    int xx1 = xx0 + 8;

    float d[2][8][4];
#pragma unroll
    for (int f = 0; f < 2; f++)
#pragma unroll
        for (int nb = 0; nb < 8; nb++)
#pragma unroll
            for (int i = 0; i < 4; i++) d[f][nb][i] = 0.f;

#pragma unroll
    for (int sk = 0; sk < 2; sk++) {
        int k0 = sk * 16 + cbase;
        uint32_t aHi[2][4], aLo[2][4];
#pragma unroll
        for (int f = 0; f < 2; f++) {
            int py = 2 * Y + f;
            float v00 = conv1_fetch(xb, k0,     py, x0 + xx0);
            float v01 = conv1_fetch(xb, k0 + 1, py, x0 + xx0);
            float v08 = conv1_fetch(xb, k0 + 8, py, x0 + xx0);
            float v09 = conv1_fetch(xb, k0 + 9, py, x0 + xx0);
            float v10 = conv1_fetch(xb, k0,     py, x0 + xx1);
            float v11 = conv1_fetch(xb, k0 + 1, py, x0 + xx1);
            float v18 = conv1_fetch(xb, k0 + 8, py, x0 + xx1);
            float v19 = conv1_fetch(xb, k0 + 9, py, x0 + xx1);
            aHi[f][0] = pack_hi2(v00, v01); aLo[f][0] = pack_lo2(v00, v01);
            aHi[f][1] = pack_hi2(v10, v11); aLo[f][1] = pack_lo2(v10, v11);
            aHi[f][2] = pack_hi2(v08, v09); aLo[f][2] = pack_lo2(v08, v09);
            aHi[f][3] = pack_hi2(v18, v19); aLo[f][3] = pack_lo2(v18, v19);
        }
#pragma unroll
        for (int nb = 0; nb < 8; nb++) {
            int n = nb * 8 + g;
            uint2 bh = g_wc1[0][n][sk][t];
            uint2 bl = g_wc1[1][n][sk][t];
#pragma unroll
            for (int f = 0; f < 2; f++) {
                mma16816(d[f][nb], aHi[f], bh.x, bh.y);
                mma16816(d[f][nb], aHi[f], bl.x, bl.y);
                mma16816(d[f][nb], aLo[f], bh.x, bh.y);
            }
        }
    }

    // 2-pass epilogue: pass f writes frag f rows (xx), pool across passes.
    float pm[16];
#pragma unroll
    for (int f = 0; f < 2; f++) {
#pragma unroll
        for (int nb = 0; nb < 8; nb++) {
            int c = nb * 8 + cbase;
            s[xx0 * 65 + c]     = d[f][nb][0];
            s[xx0 * 65 + c + 1] = d[f][nb][1];
            s[xx1 * 65 + c]     = d[f][nb][2];
            s[xx1 * 65 + c + 1] = d[f][nb][3];
        }
        __syncthreads();
#pragma unroll
        for (int k = 0; k < 16; k++) {
            int oi = k * 256 + tid;
            int oc = oi & 63;
            int j = oi >> 6;
            float m = fmaxf(s[(2 * j) * 65 + oc], s[(2 * j + 1) * 65 + oc]);
            if (f == 0) {
                pm[k] = m;
            } else {
                int st = oc >> 5;
                int ocl = oc & 31;
                float bi = st ? b_ir[ocl] : b_rgb[ocl];
                float v = fmaxf(fmaxf(pm[k], m) + bi, 0.f);
                size_t pix = (((size_t)(b * 256 + Y)) * 256 + (x0 >> 1) + j) * 32 + ocl;
                g_p1h[st][pix] = bf_hi(v);
                g_p1l[st][pix] = bf_lo(v);
            }
        }
        __syncthreads();
    }
}

// ======================= conv2 (per stream) ================================
// grid 2048: (b, pooled row Y 0..127, x-group of 128 pre-pool cols).
// M=256 (2 dy frags x 128 xx), N=64 oc, K = 9 taps x 32 ic.
__global__ void __launch_bounds__(256, 1)
conv2_mma(int which, const float* __restrict__ bias) {
    __shared__ float s[128 * 65];
    int tid = threadIdx.x;
    int wid = tid >> 5;
    int lane = tid & 31;
    int g = lane >> 2;
    int t = lane & 3;
    int cbase = 2 * t;
    int bid = blockIdx.x;
    int x0 = (bid & 1) * 128;
    int Y = (bid >> 1) & 127;
    int b = bid >> 8;
    const u16* ph = g_p1h[which];
    const u16* pl = g_p1l[which];
    int ch_off = which * 64;
    int wm0 = which * 9;

    int xx0 = wid * 16 + g;
    int xx1 = xx0 + 8;

    float d[2][8][4];
#pragma unroll
    for (int f = 0; f < 2; f++)
#pragma unroll
        for (int nb = 0; nb < 8; nb++)
#pragma unroll
            for (int i = 0; i < 4; i++) d[f][nb][i] = 0.f;

    for (int tap = 0; tap < 9; tap++) {
        int kh = tap / 3;
        int kw = tap - kh * 3;
        int gxA = x0 + xx0 + kw - 1;
        int gxB = x0 + xx1 + kw - 1;
        bool okxA = (gxA >= 0 && gxA < 256);
        bool okxB = (gxB >= 0 && gxB < 256);
        bool okf[2][2];
        size_t off[2][2];
#pragma unroll
        for (int f = 0; f < 2; f++) {
            int gy = 2 * Y + f + kh - 1;
            bool oky = (gy >= 0 && gy < 256);
            okf[f][0] = oky && okxA;
            okf[f][1] = oky && okxB;
            off[f][0] = okf[f][0] ? (((size_t)(b * 256 + gy)) * 256 + gxA) * 32 : 0;
            off[f][1] = okf[f][1] ? (((size_t)(b * 256 + gy)) * 256 + gxB) * 32 : 0;
        }
        const uint2(*wh)[2][4] = g_wc2[0][wm0 + tap];
        const uint2(*wl)[2][4] = g_wc2[1][wm0 + tap];
#pragma unroll
        for (int sk = 0; sk < 2; sk++) {
            int ic = sk * 16 + cbase;
            uint32_t aHi[2][4], aLo[2][4];
#pragma unroll
            for (int f = 0; f < 2; f++) {
                aHi[f][0] = ldp(ph, okf[f][0], off[f][0] + ic);
                aHi[f][1] = ldp(ph, okf[f][1], off[f][1] + ic);
                aHi[f][2] = ldp(ph, okf[f][0], off[f][0] + ic + 8);
                aHi[f][3] = ldp(ph, okf[f][1], off[f][1] + ic + 8);
                aLo[f][0] = ldp(pl, okf[f][0], off[f][0] + ic);
                aLo[f][1] = ldp(pl, okf[f][1], off[f][1] + ic);
                aLo[f][2] = ldp(pl, okf[f][0], off[f][0] + ic + 8);
                aLo[f][3] = ldp(pl, okf[f][1], off[f][1] + ic + 8);
            }
#pragma unroll
            for (int nb = 0; nb < 8; nb++) {
                int n = nb * 8 + g;
                uint2 bh = wh[n][sk][t];
                uint2 bl = wl[n][sk][t];
#pragma unroll
                for (int f = 0; f < 2; f++) {
                    mma16816(d[f][nb], aHi[f], bh.x, bh.y);
                    mma16816(d[f][nb], aHi[f], bl.x, bl.y);
                    mma16816(d[f][nb], aLo[f], bh.x, bh.y);
                }
            }
        }
    }

    float pm[16];
#pragma unroll
    for (int f = 0; f < 2; f++) {
#pragma unroll
        for (int nb = 0; nb < 8; nb++) {
            int c = nb * 8 + cbase;
            s[xx0 * 65 + c]     = d[f][nb][0];
            s[xx0 * 65 + c + 1] = d[f][nb][1];
            s[xx1 * 65 + c]     = d[f][nb][2];
            s[xx1 * 65 + c + 1] = d[f][nb][3];
        }
        __syncthreads();
#pragma unroll
        for (int k = 0; k < 16; k++) {
            int oi = k * 256 + tid;
            int oc = oi & 63;
            int j = oi >> 6;
            float m = fmaxf(s[(2 * j) * 65 + oc], s[(2 * j + 1) * 65 + oc]);
            if (f == 0) {
                pm[k] = m;
            } else {
                float v = fmaxf(fmaxf(pm[k], m) + bias[oc], 0.f);
                size_t pix = (((size_t)(b * 128 + Y)) * 128 + (x0 >> 1) + j) * 128 + ch_off + oc;
                g_cch[pix] = bf_hi(v);
                g_ccl[pix] = bf_lo(v);
            }
        }
        __syncthreads();
    }
}

// ======================= fuse (128->128 conv + relu + mean) ================
// grid 1024: (b, y-pair 0..63, oc-half). M=256 (2 y rows x 128 x), N=64,
// K = 9 taps x 128 ic.
__global__ void __launch_bounds__(256, 1)
fuse_mma(const float* __restrict__ bias) {
    __shared__ float s[128 * 65];
    int tid = threadIdx.x;
    int wid = tid >> 5;
    int lane = tid & 31;
    int g = lane >> 2;
    int t = lane & 3;
    int cbase = 2 * t;
    int bid = blockIdx.x;
    int nh = bid & 1;
    int yp = (bid >> 1) & 63;
    int b = bid >> 7;
    int y0 = 2 * yp;

    int xx0 = wid * 16 + g;
    int xx1 = xx0 + 8;

    float d[2][8][4];
#pragma unroll
    for (int f = 0; f < 2; f++)
#pragma unroll
        for (int nb = 0; nb < 8; nb++)
#pragma unroll
            for (int i = 0; i < 4; i++) d[f][nb][i] = 0.f;

    for (int tap = 0; tap < 9; tap++) {
        int kh = tap / 3;
        int kw = tap - kh * 3;
        int gxA = xx0 + kw - 1;
        int gxB = xx1 + kw - 1;
        bool okxA = (gxA >= 0 && gxA < 128);
        bool okxB = (gxB >= 0 && gxB < 128);
        bool okf[2][2];
        size_t off[2][2];
#pragma unroll
        for (int f = 0; f < 2; f++) {
            int gy = y0 + f + kh - 1;
            bool oky = (gy >= 0 && gy < 128);
            okf[f][0] = oky && okxA;
            okf[f][1] = oky && okxB;
            off[f][0] = okf[f][0] ? (((size_t)(b * 128 + gy)) * 128 + gxA) * 128 : 0;
            off[f][1] = okf[f][1] ? (((size_t)(b * 128 + gy)) * 128 + gxB) * 128 : 0;
        }
        const uint2(*wh)[8][4] = g_wf[0][tap];
        const uint2(*wl)[8][4] = g_wf[1][tap];
#pragma unroll
        for (int sk = 0; sk < 8; sk++) {
            int ic = sk * 16 + cbase;
            uint32_t aHi[2][4], aLo[2][4];
#pragma unroll
            for (int f = 0; f < 2; f++) {
                aHi[f][0] = ldp(g_cch, okf[f][0], off[f][0] + ic);
                aHi[f][1] = ldp(g_cch, okf[f][1], off[f][1] + ic);
                aHi[f][2] = ldp(g_cch, okf[f][0], off[f][0] + ic + 8);
                aHi[f][3] = ldp(g_cch, okf[f][1], off[f][1] + ic + 8);
                aLo[f][0] = ldp(g_ccl, okf[f][0], off[f][0] + ic);
                aLo[f][1] = ldp(g_ccl, okf[f][1], off[f][1] + ic);
                aLo[f][2] = ldp(g_ccl, okf[f][0], off[f][0] + ic + 8);
                aLo[f][3] = ldp(g_ccl, okf[f][1], off[f][1] + ic + 8);
            }
#pragma unroll
            for (int nb = 0; nb < 8; nb++) {
                int n = nh * 64 + nb * 8 + g;
                uint2 bh = wh[n][sk][t];
                uint2 bl = wl[n][sk][t];
#pragma unroll
                for (int f = 0; f < 2; f++) {
                    mma16816(d[f][nb], aHi[f], bh.x, bh.y);
                    mma16816(d[f][nb], aHi[f], bl.x, bl.y);
                    mma16816(d[f][nb], aLo[f], bh.x, bh.y);
                }
            }
        }
    }

    // 2-pass epilogue: bias+relu into smem, column partial sums, atomic mean.
    int col = tid & 63;
    int q = tid >> 6;
    float csum = 0.f;
#pragma unroll
    for (int f = 0; f < 2; f++) {
#pragma unroll
        for (int nb = 0; nb < 8; nb++) {
            int c = nb * 8 + cbase;
            float b0 = bias[nh * 64 + c];
            float b1 = bias[nh * 64 + c + 1];
            s[xx0 * 65 + c]     = fmaxf(d[f][nb][0] + b0, 0.f);
            s[xx0 * 65 + c + 1] = fmaxf(d[f][nb][1] + b1, 0.f);
            s[xx1 * 65 + c]     = fmaxf(d[f][nb][2] + b0, 0.f);
            s[xx1 * 65 + c + 1] = fmaxf(d[f][nb][3] + b1, 0.f);
        }
        __syncthreads();
        for (int r = q * 32; r < q * 32 + 32; r++) csum += s[r * 65 + col];
        __syncthreads();
    }
    atomicAdd(&g_mean[b * 128 + nh * 64 + col], csum);
}

// ======================= head: det 1x1 + sigmoid + NMS =====================
__global__ void head_kernel(const float* __restrict__ det_w,
                            const float* __restrict__ det_b,
                            float* __restrict__ out) {
    int b = blockIdx.x;
    int lane = threadIdx.x;
    __shared__ float pv[18];
    if (lane < 18) {
        float acc = det_b[lane];
        for (int c = 0; c < 128; c++)
            acc = fmaf(det_w[lane * 128 + c], g_mean[b * 128 + c] * (1.f / 16384.f), acc);
        pv[lane] = acc;
    }
    __syncthreads();
    if (lane != 0) return;

    for (int i = 0; i < 18; i++) out[b * 18 + i] = pv[i];

    float bx[3][4], sc[3], eff[3];
    bool conf[3];
    for (int a = 0; a < 3; a++) {
        for (int k = 0; k < 4; k++) bx[a][k] = pv[a * 6 + k];
        sc[a] = 1.f / (1.f + expf(-pv[a * 6 + 4]));
        conf[a] = sc[a] > 0.5f;
        eff[a] = conf[a] ? sc[a] : -INFINITY;
    }
    int order[3];
    bool used[3] = {false, false, false};
    for (int i = 0; i < 3; i++) {
        int best = -1;
        for (int a = 0; a < 3; a++)
            if (!used[a] && (best < 0 || eff[a] > eff[best])) best = a;
        order[i] = best;
        used[best] = true;
    }
    float ox1[3], oy1[3], ox2[3], oy2[3], area[3];
    for (int i = 0; i < 3; i++) {
        int a = order[i];
        ox1[i] = bx[a][0]; oy1[i] = bx[a][1]; ox2[i] = bx[a][2]; oy2[i] = bx[a][3];
        area[i] = (ox2[i] - ox1[i]) * (oy2[i] - oy1[i]);
    }
    bool keep_s[3];
    bool sup[3] = {false, false, false};
    for (int i = 0; i < 3; i++) {
        bool valid = !sup[i];
        keep_s[i] = valid;
        if (valid) {
            for (int j = i + 1; j < 3; j++) {
                float ix1 = fmaxf(ox1[i], ox1[j]);
                float iy1 = fmaxf(oy1[i], oy1[j]);
                float ix2 = fminf(ox2[i], ox2[j]);
                float iy2 = fminf(oy2[i], oy2[j]);
                float inter = fmaxf(ix2 - ix1, 0.f) * fmaxf(iy2 - iy1, 0.f);
                float iou = inter / (area[i] + area[j] - inter);
                if (iou > 0.5f) sup[j] = true;
            }
        }
    }
    bool kp[3];
    for (int i = 0; i < 3; i++) kp[order[i]] = keep_s[i];
    for (int a = 0; a < 3; a++) kp[a] = kp[a] && conf[a];

    for (int a = 0; a < 3; a++) {
        for (int k = 0; k < 4; k++) out[144 + b * 12 + a * 4 + k] = bx[a][k];
        out[240 + b * 3 + a] = sc[a];
        out[264 + b * 3 + a] = kp[a] ? 1.f : 0.f;
    }
}

// ===========================================================================
extern "C" void kernel_launch(void* const* d_in, const int* in_sizes, int n_in,
                              void* d_out, int out_size) {
    const float* x      = (const float*)d_in[0];
    const float* rgb_w1 = (const float*)d_in[1];
    const float* rgb_b1 = (const float*)d_in[2];
    const float* rgb_w2 = (const float*)d_in[3];
    const float* rgb_b2 = (const float*)d_in[4];
    const float* ir_w1  = (const float*)d_in[5];
    const float* ir_b1  = (const float*)d_in[6];
    const float* ir_w2  = (const float*)d_in[7];
    const float* ir_b2  = (const float*)d_in[8];
    const float* fuse_w = (const float*)d_in[9];
    const float* fuse_b = (const float*)d_in[10];
    const float* det_w  = (const float*)d_in[11];
    const float* det_b  = (const float*)d_in[12];
    float* out = (float*)d_out;

    zero_mean_kernel<<<1, 1024>>>();
    xform_w1<<<2, 256>>>(rgb_w1, ir_w1);
    xform_w2<<<18, 256>>>(rgb_w2, 0);
    xform_w2<<<18, 256>>>(ir_w2, 1);
    xform_wf<<<144, 256>>>(fuse_w);

    conv1_mma<<<8192, 256>>>(x, rgb_b1, ir_b1);
    conv2_mma<<<2048, 256>>>(0, rgb_b2);
    conv2_mma<<<2048, 256>>>(1, ir_b2);
    fuse_mma<<<1024, 256>>>(fuse_b);
    head_kernel<<<8, 32>>>(det_w, det_b, out);
}

// round 11
// speedup vs baseline: 4.4646x; 1.1403x over previous
#include <cuda_runtime.h>
#include <cuda_bf16.h>
#include <stdint.h>
#include <math.h>

#define BATCH 8
#define H0 512

typedef unsigned short u16;

// ------------------------- scratch globals (no allocs) ---------------------
// pool1 per stream, halo-padded channel-last bf16 hi/lo: [b][y258][x258][c32]
#define P1W 258
#define NP1 ((size_t)BATCH * P1W * P1W * 32)
__device__ u16 g_p1h[2][NP1];
__device__ u16 g_p1l[2][NP1];
// concat halo-padded channel-last bf16 hi/lo: [b][y130][x130][c128]
#define CCW 130
#define NCC ((size_t)BATCH * CCW * CCW * 128)
__device__ u16 g_cch[NCC];
__device__ u16 g_ccl[NCC];
__device__ float g_mean[BATCH * 128];

// pre-packed bf16 weights as uint2 {pair(p0), pair(p0+4)}: [hi/lo][...][oc][sk][t]
__device__ uint2 g_wc1[2][64][2][4];
__device__ uint2 g_wc2[2][18][64][2][4];
__device__ uint2 g_wf[2][9][128][8][4];

// ------------------------- numeric helpers ---------------------------------
__device__ __forceinline__ u16 bf_hi(float v) {
    return __bfloat16_as_ushort(__float2bfloat16(v));
}
__device__ __forceinline__ u16 bf_lo(float v) {
    float h = __bfloat162float(__float2bfloat16(v));
    return __bfloat16_as_ushort(__float2bfloat16(v - h));
}
__device__ __forceinline__ uint32_t pack_hi2(float v0, float v1) {
    return (uint32_t)bf_hi(v0) | ((uint32_t)bf_hi(v1) << 16);
}
__device__ __forceinline__ uint32_t pack_lo2(float v0, float v1) {
    return (uint32_t)bf_lo(v0) | ((uint32_t)bf_lo(v1) << 16);
}

// m16n8k16 bf16 HMMA, D += A*B (fp32 accumulate)
__device__ __forceinline__ void mma16816(float* d, const uint32_t* a, uint32_t b0, uint32_t b1) {
    asm volatile(
        "mma.sync.aligned.m16n8k16.row.col.f32.bf16.bf16.f32 "
        "{%0,%1,%2,%3}, {%4,%5,%6,%7}, {%8,%9}, {%0,%1,%2,%3};"
        : "+f"(d[0]), "+f"(d[1]), "+f"(d[2]), "+f"(d[3])
        : "r"(a[0]), "r"(a[1]), "r"(a[2]), "r"(a[3]), "r"(b0), "r"(b1));
}

__device__ __forceinline__ uint32_t ld32(const u16* p) {
    return *(const uint32_t*)p;
}

// ------------------------- init kernels ------------------------------------
__global__ void zero_mean_kernel() {
    int i = threadIdx.x;
    if (i < BATCH * 128) g_mean[i] = 0.f;
}

// zero the halo ring of all 4 pool1 planes. 1028 halo px/batch, 32 ch.
__global__ void halo_p1_kernel() {
    int idx = blockIdx.x * 256 + threadIdx.x;       // 8 b x 1028 px x 32 c
    if (idx >= BATCH * 1028 * 32) return;
    int c = idx & 31;
    int r = idx >> 5;
    int b = r / 1028;
    int p = r - b * 1028;
    int y, x;
    if (p < 258)      { y = 0;           x = p; }
    else if (p < 516) { y = 257;         x = p - 258; }
    else if (p < 772) { y = p - 516 + 1; x = 0; }
    else              { y = p - 772 + 1; x = 257; }
    size_t i = (((size_t)(b * P1W + y)) * P1W + x) * 32 + c;
    g_p1h[0][i] = 0; g_p1h[1][i] = 0;
    g_p1l[0][i] = 0; g_p1l[1][i] = 0;
}

// zero the halo ring of concat planes. 516 halo px/batch, 128 ch.
__global__ void halo_cc_kernel() {
    int idx = blockIdx.x * 256 + threadIdx.x;       // 8 b x 516 px x 128 c
    if (idx >= BATCH * 516 * 128) return;
    int c = idx & 127;
    int r = idx >> 7;
    int b = r / 516;
    int p = r - b * 516;
    int y, x;
    if (p < 130)      { y = 0;           x = p; }
    else if (p < 260) { y = 129;         x = p - 130; }
    else if (p < 388) { y = p - 260 + 1; x = 0; }
    else              { y = p - 388 + 1; x = 129; }
    size_t i = (((size_t)(b * CCW + y)) * CCW + x) * 128 + c;
    g_cch[i] = 0;
    g_ccl[i] = 0;
}

// ------------------------- weight transforms -------------------------------
__device__ __forceinline__ float w1elem(const float* w, int ocl, int kk) {
    if (kk >= 27) return 0.f;
    int tap = kk / 3;
    int ic = kk - 3 * tap;
    return w[ocl * 27 + ic * 9 + tap];
}

__global__ void xform_w1(const float* __restrict__ wr, const float* __restrict__ wi) {
    int idx = blockIdx.x * 256 + threadIdx.x;       // 64 oc x 2 sk x 4 t
    if (idx >= 512) return;
    int oc = idx >> 3, sk = (idx >> 2) & 1, t = idx & 3;
    const float* w = (oc < 32) ? wr : wi;
    int ocl = oc & 31;
    int pA = t + 8 * sk, pB = pA + 4;
    float a0 = w1elem(w, ocl, 2 * pA), a1 = w1elem(w, ocl, 2 * pA + 1);
    float b0 = w1elem(w, ocl, 2 * pB), b1 = w1elem(w, ocl, 2 * pB + 1);
    g_wc1[0][oc][sk][t] = make_uint2(pack_hi2(a0, a1), pack_hi2(b0, b1));
    g_wc1[1][oc][sk][t] = make_uint2(pack_lo2(a0, a1), pack_lo2(b0, b1));
}

__global__ void xform_w2(const float* __restrict__ w, int sidx) {
    int idx = blockIdx.x * 256 + threadIdx.x;       // 9 tap x 64 oc x 2 sk x 4 t
    if (idx >= 9 * 512) return;
    int tap = idx / 512;
    int rem = idx & 511;
    int oc = rem >> 3, sk = (rem >> 2) & 1, t = rem & 3;
    int pA = t + 8 * sk, pB = pA + 4;
    float a0 = w[oc * 288 + (2 * pA) * 9 + tap],     a1 = w[oc * 288 + (2 * pA + 1) * 9 + tap];
    float b0 = w[oc * 288 + (2 * pB) * 9 + tap],     b1 = w[oc * 288 + (2 * pB + 1) * 9 + tap];
    int mi = sidx * 9 + tap;
    g_wc2[0][mi][oc][sk][t] = make_uint2(pack_hi2(a0, a1), pack_hi2(b0, b1));
    g_wc2[1][mi][oc][sk][t] = make_uint2(pack_lo2(a0, a1), pack_lo2(b0, b1));
}

__global__ void xform_wf(const float* __restrict__ w) {
    int idx = blockIdx.x * 256 + threadIdx.x;       // 9 tap x 128 oc x 8 sk x 4 t
    if (idx >= 9 * 4096) return;
    int tap = idx >> 12;
    int rem = idx & 4095;
    int oc = rem >> 5, sk = (rem >> 2) & 7, t = rem & 3;
    int pA = t + 8 * sk, pB = pA + 4;
    float a0 = w[(oc * 128 + 2 * pA) * 9 + tap],     a1 = w[(oc * 128 + 2 * pA + 1) * 9 + tap];
    float b0 = w[(oc * 128 + 2 * pB) * 9 + tap],     b1 = w[(oc * 128 + 2 * pB + 1) * 9 + tap];
    g_wf[0][tap][oc][sk][t] = make_uint2(pack_hi2(a0, a1), pack_hi2(b0, b1));
    g_wf[1][tap][oc][sk][t] = make_uint2(pack_lo2(a0, a1), pack_lo2(b0, b1));
}

// ======================= conv1 (both streams in one GEMM) ==================
__device__ __forceinline__ float conv1_fetch(const float* xb, int kk, int py, int px) {
    if (kk >= 27) return 0.f;
    int tap = kk / 3;
    int ic = kk - tap * 3;
    int kh = tap / 3;
    int kw = tap - kh * 3;
    int gy = py + kh - 1;
    int gx = px + kw - 1;
    if (gy < 0 || gy >= H0 || gx < 0 || gx >= H0) return 0.f;
    return xb[(size_t)ic * H0 * H0 + (size_t)gy * H0 + gx];
}

// grid 8192: (b, pooled row Y 0..255, x-group of 128 pre-pool cols).
// M=256 (2 dy frags x 128 xx), N=64, K=32 (27 used).
__global__ void __launch_bounds__(256, 2)
conv1_mma(const float* __restrict__ x,
          const float* __restrict__ b_rgb,
          const float* __restrict__ b_ir) {
    __shared__ float s[128 * 65];
    int tid = threadIdx.x;
    int wid = tid >> 5;
    int lane = tid & 31;
    int g = lane >> 2;
    int t = lane & 3;
    int cbase = 2 * t;
    int bid = blockIdx.x;
    int x0 = (bid & 3) * 128;
    int Y = (bid >> 2) & 255;
    int b = bid >> 10;
    const float* xb = x + (size_t)b * 3 * H0 * H0;

    int xx0 = wid * 16 + g;
    int xx1 = xx0 + 8;

    float d[2][8][4];
#pragma unroll
    for (int f = 0; f < 2; f++)
#pragma unroll
        for (int nb = 0; nb < 8; nb++)
#pragma unroll
            for (int i = 0; i < 4; i++) d[f][nb][i] = 0.f;

#pragma unroll
    for (int sk = 0; sk < 2; sk++) {
        int k0 = sk * 16 + cbase;
        uint32_t aHi[2][4], aLo[2][4];
#pragma unroll
        for (int f = 0; f < 2; f++) {
            int py = 2 * Y + f;
            float v00 = conv1_fetch(xb, k0,     py, x0 + xx0);
            float v01 = conv1_fetch(xb, k0 + 1, py, x0 + xx0);
            float v08 = conv1_fetch(xb, k0 + 8, py, x0 + xx0);
            float v09 = conv1_fetch(xb, k0 + 9, py, x0 + xx0);
            float v10 = conv1_fetch(xb, k0,     py, x0 + xx1);
            float v11 = conv1_fetch(xb, k0 + 1, py, x0 + xx1);
            float v18 = conv1_fetch(xb, k0 + 8, py, x0 + xx1);
            float v19 = conv1_fetch(xb, k0 + 9, py, x0 + xx1);
            aHi[f][0] = pack_hi2(v00, v01); aLo[f][0] = pack_lo2(v00, v01);
            aHi[f][1] = pack_hi2(v10, v11); aLo[f][1] = pack_lo2(v10, v11);
            aHi[f][2] = pack_hi2(v08, v09); aLo[f][2] = pack_lo2(v08, v09);
            aHi[f][3] = pack_hi2(v18, v19); aLo[f][3] = pack_lo2(v18, v19);
        }
#pragma unroll
        for (int nb = 0; nb < 8; nb++) {
            int n = nb * 8 + g;
            uint2 bh = g_wc1[0][n][sk][t];
            uint2 bl = g_wc1[1][n][sk][t];
#pragma unroll
            for (int f = 0; f < 2; f++) {
                mma16816(d[f][nb], aHi[f], bh.x, bh.y);
                mma16816(d[f][nb], aHi[f], bl.x, bl.y);
                mma16816(d[f][nb], aLo[f], bh.x, bh.y);
            }
        }
    }

    // 2-pass epilogue: pass f writes frag f rows (xx), pool across passes.
    float pm[16];
#pragma unroll
    for (int f = 0; f < 2; f++) {
#pragma unroll
        for (int nb = 0; nb < 8; nb++) {
            int c = nb * 8 + cbase;
            s[xx0 * 65 + c]     = d[f][nb][0];
            s[xx0 * 65 + c + 1] = d[f][nb][1];
            s[xx1 * 65 + c]     = d[f][nb][2];
            s[xx1 * 65 + c + 1] = d[f][nb][3];
        }
        __syncthreads();
#pragma unroll
        for (int k = 0; k < 16; k++) {
            int oi = k * 256 + tid;
            int oc = oi & 63;
            int j = oi >> 6;
            float m = fmaxf(s[(2 * j) * 65 + oc], s[(2 * j + 1) * 65 + oc]);
            if (f == 0) {
                pm[k] = m;
            } else {
                int st = oc >> 5;
                int ocl = oc & 31;
                float bi = st ? b_ir[ocl] : b_rgb[ocl];
                float v = fmaxf(fmaxf(pm[k], m) + bi, 0.f);
                size_t pix = (((size_t)(b * P1W + Y + 1)) * P1W + (x0 >> 1) + j + 1) * 32 + ocl;
                g_p1h[st][pix] = bf_hi(v);
                g_p1l[st][pix] = bf_lo(v);
            }
        }
        __syncthreads();
    }
}

// ======================= conv2 (both streams, one launch) ==================
// grid 4096: (which, b, pooled row Y 0..127, x-group of 128 pre-pool cols).
// M=256 (2 dy frags x 128 xx), N=64 oc, K = 9 taps x 32 ic. Padded loads,
// fully unrolled taps -> immediate-offset unconditional LDG.
__global__ void __launch_bounds__(256, 2)
conv2_mma(const float* __restrict__ bias_r, const float* __restrict__ bias_i) {
    __shared__ float s[128 * 65];
    int tid = threadIdx.x;
    int wid = tid >> 5;
    int lane = tid & 31;
    int g = lane >> 2;
    int t = lane & 3;
    int cbase = 2 * t;
    int bid = blockIdx.x;
    int x0 = (bid & 1) * 128;
    int Y = (bid >> 1) & 127;
    int b = (bid >> 8) & 7;
    int which = bid >> 11;
    const u16* ph = g_p1h[which];
    const u16* pl = g_p1l[which];
    const float* bias = which ? bias_i : bias_r;
    int ch_off = which * 64;
    int wm0 = which * 9;

    int xx0 = wid * 16 + g;
    int xx1 = xx0 + 8;

    // padded base offsets (center pixel of each fragment row)
    size_t pb[2][2];
#pragma unroll
    for (int f = 0; f < 2; f++) {
        pb[f][0] = (((size_t)(b * P1W + 2 * Y + f + 1)) * P1W + (x0 + xx0 + 1)) * 32;
        pb[f][1] = (((size_t)(b * P1W + 2 * Y + f + 1)) * P1W + (x0 + xx1 + 1)) * 32;
    }

    float d[2][8][4];
#pragma unroll
    for (int f = 0; f < 2; f++)
#pragma unroll
        for (int nb = 0; nb < 8; nb++)
#pragma unroll
            for (int i = 0; i < 4; i++) d[f][nb][i] = 0.f;

#pragma unroll
    for (int tap = 0; tap < 9; tap++) {
        const int kh = tap / 3;
        const int kw = tap - kh * 3;
        const ptrdiff_t to = ((ptrdiff_t)(kh - 1) * P1W + (kw - 1)) * 32;
        const uint2(*wh)[2][4] = g_wc2[0][wm0 + tap];
        const uint2(*wl)[2][4] = g_wc2[1][wm0 + tap];
#pragma unroll
        for (int sk = 0; sk < 2; sk++) {
            int ic = sk * 16 + cbase;
            uint32_t aHi[2][4], aLo[2][4];
#pragma unroll
            for (int f = 0; f < 2; f++) {
                aHi[f][0] = ld32(ph + pb[f][0] + to + ic);
                aHi[f][1] = ld32(ph + pb[f][1] + to + ic);
                aHi[f][2] = ld32(ph + pb[f][0] + to + ic + 8);
                aHi[f][3] = ld32(ph + pb[f][1] + to + ic + 8);
                aLo[f][0] = ld32(pl + pb[f][0] + to + ic);
                aLo[f][1] = ld32(pl + pb[f][1] + to + ic);
                aLo[f][2] = ld32(pl + pb[f][0] + to + ic + 8);
                aLo[f][3] = ld32(pl + pb[f][1] + to + ic + 8);
            }
#pragma unroll
            for (int nb = 0; nb < 8; nb++) {
                int n = nb * 8 + g;
                uint2 bh = wh[n][sk][t];
                uint2 bl = wl[n][sk][t];
#pragma unroll
                for (int f = 0; f < 2; f++) {
                    mma16816(d[f][nb], aHi[f], bh.x, bh.y);
                    mma16816(d[f][nb], aHi[f], bl.x, bl.y);
                    mma16816(d[f][nb], aLo[f], bh.x, bh.y);
                }
            }
        }
    }

    float pm[16];
#pragma unroll
    for (int f = 0; f < 2; f++) {
#pragma unroll
        for (int nb = 0; nb < 8; nb++) {
            int c = nb * 8 + cbase;
            s[xx0 * 65 + c]     = d[f][nb][0];
            s[xx0 * 65 + c + 1] = d[f][nb][1];
            s[xx1 * 65 + c]     = d[f][nb][2];
            s[xx1 * 65 + c + 1] = d[f][nb][3];
        }
        __syncthreads();
#pragma unroll
        for (int k = 0; k < 16; k++) {
            int oi = k * 256 + tid;
            int oc = oi & 63;
            int j = oi >> 6;
            float m = fmaxf(s[(2 * j) * 65 + oc], s[(2 * j + 1) * 65 + oc]);
            if (f == 0) {
                pm[k] = m;
            } else {
                float v = fmaxf(fmaxf(pm[k], m) + bias[oc], 0.f);
                size_t pix = (((size_t)(b * CCW + Y + 1)) * CCW + (x0 >> 1) + j + 1) * 128 + ch_off + oc;
                g_cch[pix] = bf_hi(v);
                g_ccl[pix] = bf_lo(v);
            }
        }
        __syncthreads();
    }
}

// ======================= fuse (128->128 conv + relu + mean) ================
// grid 1024: (b, y-pair 0..63, oc-half). M=256 (2 y rows x 128 x), N=64,
// K = 9 taps x 128 ic. Padded + unrolled.
__global__ void __launch_bounds__(256, 2)
fuse_mma(const float* __restrict__ bias) {
    __shared__ float s[128 * 65];
    int tid = threadIdx.x;
    int wid = tid >> 5;
    int lane = tid & 31;
    int g = lane >> 2;
    int t = lane & 3;
    int cbase = 2 * t;
    int bid = blockIdx.x;
    int nh = bid & 1;
    int yp = (bid >> 1) & 63;
    int b = bid >> 7;
    int y0 = 2 * yp;

    int xx0 = wid * 16 + g;
    int xx1 = xx0 + 8;

    size_t pb[2][2];
#pragma unroll
    for (int f = 0; f < 2; f++) {
        pb[f][0] = (((size_t)(b * CCW + y0 + f + 1)) * CCW + (xx0 + 1)) * 128;
        pb[f][1] = (((size_t)(b * CCW + y0 + f + 1)) * CCW + (xx1 + 1)) * 128;
    }

    float d[2][8][4];
#pragma unroll
    for (int f = 0; f < 2; f++)
#pragma unroll
        for (int nb = 0; nb < 8; nb++)
#pragma unroll
            for (int i = 0; i < 4; i++) d[f][nb][i] = 0.f;

#pragma unroll
    for (int tap = 0; tap < 9; tap++) {
        const int kh = tap / 3;
        const int kw = tap - kh * 3;
        const ptrdiff_t to = ((ptrdiff_t)(kh - 1) * CCW + (kw - 1)) * 128;
        const uint2(*wh)[8][4] = g_wf[0][tap];
        const uint2(*wl)[8][4] = g_wf[1][tap];
#pragma unroll
        for (int sk = 0; sk < 8; sk++) {
            int ic = sk * 16 + cbase;
            uint32_t aHi[2][4], aLo[2][4];
#pragma unroll
            for (int f = 0; f < 2; f++) {
                aHi[f][0] = ld32(g_cch + pb[f][0] + to + ic);
                aHi[f][1] = ld32(g_cch + pb[f][1] + to + ic);
                aHi[f][2] = ld32(g_cch + pb[f][0] + to + ic + 8);
                aHi[f][3] = ld32(g_cch + pb[f][1] + to + ic + 8);
                aLo[f][0] = ld32(g_ccl + pb[f][0] + to + ic);
                aLo[f][1] = ld32(g_ccl + pb[f][1] + to + ic);
                aLo[f][2] = ld32(g_ccl + pb[f][0] + to + ic + 8);
                aLo[f][3] = ld32(g_ccl + pb[f][1] + to + ic + 8);
            }
#pragma unroll
            for (int nb = 0; nb < 8; nb++) {
                int n = nh * 64 + nb * 8 + g;
                uint2 bh = wh[n][sk][t];
                uint2 bl = wl[n][sk][t];
#pragma unroll
                for (int f = 0; f < 2; f++) {
                    mma16816(d[f][nb], aHi[f], bh.x, bh.y);
                    mma16816(d[f][nb], aHi[f], bl.x, bl.y);
                    mma16816(d[f][nb], aLo[f], bh.x, bh.y);
                }
            }
        }
    }

    // 2-pass epilogue: bias+relu into smem, column partial sums, atomic mean.
    int col = tid & 63;
    int q = tid >> 6;
    float csum = 0.f;
#pragma unroll
    for (int f = 0; f < 2; f++) {
#pragma unroll
        for (int nb = 0; nb < 8; nb++) {
            int c = nb * 8 + cbase;
            float b0 = bias[nh * 64 + c];
            float b1 = bias[nh * 64 + c + 1];
            s[xx0 * 65 + c]     = fmaxf(d[f][nb][0] + b0, 0.f);
            s[xx0 * 65 + c + 1] = fmaxf(d[f][nb][1] + b1, 0.f);
            s[xx1 * 65 + c]     = fmaxf(d[f][nb][2] + b0, 0.f);
            s[xx1 * 65 + c + 1] = fmaxf(d[f][nb][3] + b1, 0.f);
        }
        __syncthreads();
        for (int r = q * 32; r < q * 32 + 32; r++) csum += s[r * 65 + col];
        __syncthreads();
    }
    atomicAdd(&g_mean[b * 128 + nh * 64 + col], csum);
}

// ======================= head: det 1x1 + sigmoid + NMS =====================
__global__ void head_kernel(const float* __restrict__ det_w,
                            const float* __restrict__ det_b,
                            float* __restrict__ out) {
    int b = blockIdx.x;
    int lane = threadIdx.x;
    __shared__ float pv[18];
    if (lane < 18) {
        float acc = det_b[lane];
        for (int c = 0; c < 128; c++)
            acc = fmaf(det_w[lane * 128 + c], g_mean[b * 128 + c] * (1.f / 16384.f), acc);
        pv[lane] = acc;
    }
    __syncthreads();
    if (lane != 0) return;

    for (int i = 0; i < 18; i++) out[b * 18 + i] = pv[i];

    float bx[3][4], sc[3], eff[3];
    bool conf[3];
    for (int a = 0; a < 3; a++) {
        for (int k = 0; k < 4; k++) bx[a][k] = pv[a * 6 + k];
        sc[a] = 1.f / (1.f + expf(-pv[a * 6 + 4]));
        conf[a] = sc[a] > 0.5f;
        eff[a] = conf[a] ? sc[a] : -INFINITY;
    }
    int order[3];
    bool used[3] = {false, false, false};
    for (int i = 0; i < 3; i++) {
        int best = -1;
        for (int a = 0; a < 3; a++)
            if (!used[a] && (best < 0 || eff[a] > eff[best])) best = a;
        order[i] = best;
        used[best] = true;
    }
    float ox1[3], oy1[3], ox2[3], oy2[3], area[3];
    for (int i = 0; i < 3; i++) {
        int a = order[i];
        ox1[i] = bx[a][0]; oy1[i] = bx[a][1]; ox2[i] = bx[a][2]; oy2[i] = bx[a][3];
        area[i] = (ox2[i] - ox1[i]) * (oy2[i] - oy1[i]);
    }
    bool keep_s[3];
    bool sup[3] = {false, false, false};
    for (int i = 0; i < 3; i++) {
        bool valid = !sup[i];
        keep_s[i] = valid;
        if (valid) {
            for (int j = i + 1; j < 3; j++) {
                float ix1 = fmaxf(ox1[i], ox1[j]);
                float iy1 = fmaxf(oy1[i], oy1[j]);
                float ix2 = fminf(ox2[i], ox2[j]);
                float iy2 = fminf(oy2[i], oy2[j]);
                float inter = fmaxf(ix2 - ix1, 0.f) * fmaxf(iy2 - iy1, 0.f);
                float iou = inter / (area[i] + area[j] - inter);
                if (iou > 0.5f) sup[j] = true;
            }
        }
    }
    bool kp[3];
    for (int i = 0; i < 3; i++) kp[order[i]] = keep_s[i];
    for (int a = 0; a < 3; a++) kp[a] = kp[a] && conf[a];

    for (int a = 0; a < 3; a++) {
        for (int k = 0; k < 4; k++) out[144 + b * 12 + a * 4 + k] = bx[a][k];
        out[240 + b * 3 + a] = sc[a];
        out[264 + b * 3 + a] = kp[a] ? 1.f : 0.f;
    }
}

// ===========================================================================
extern "C" void kernel_launch(void* const* d_in, const int* in_sizes, int n_in,
                              void* d_out, int out_size) {
    const float* x      = (const float*)d_in[0];
    const float* rgb_w1 = (const float*)d_in[1];
    const float* rgb_b1 = (const float*)d_in[2];
    const float* rgb_w2 = (const float*)d_in[3];
    const float* rgb_b2 = (const float*)d_in[4];
    const float* ir_w1  = (const float*)d_in[5];
    const float* ir_b1  = (const float*)d_in[6];
    const float* ir_w2  = (const float*)d_in[7];
    const float* ir_b2  = (const float*)d_in[8];
    const float* fuse_w = (const float*)d_in[9];
    const float* fuse_b = (const float*)d_in[10];
    const float* det_w  = (const float*)d_in[11];
    const float* det_b  = (const float*)d_in[12];
    float* out = (float*)d_out;

    zero_mean_kernel<<<1, 1024>>>();
    halo_p1_kernel<<<(BATCH * 1028 * 32 + 255) / 256, 256>>>();
    halo_cc_kernel<<<(BATCH * 516 * 128 + 255) / 256, 256>>>();
    xform_w1<<<2, 256>>>(rgb_w1, ir_w1);
    xform_w2<<<18, 256>>>(rgb_w2, 0);
    xform_w2<<<18, 256>>>(ir_w2, 1);
    xform_wf<<<144, 256>>>(fuse_w);

    conv1_mma<<<8192, 256>>>(x, rgb_b1, ir_b1);
    conv2_mma<<<4096, 256>>>(rgb_b2, ir_b2);
    fuse_mma<<<1024, 256>>>(fuse_b);
    head_kernel<<<8, 32>>>(det_w, det_b, out);
}

// round 12
// speedup vs baseline: 6.8294x; 1.5297x over previous
#include <cuda_runtime.h>
#include <cuda_bf16.h>
#include <stdint.h>
#include <math.h>

#define BATCH 8
#define H0 512

typedef unsigned short u16;

// ------------------------- scratch globals (no allocs) ---------------------
// pool1 per stream, halo-padded channel-last bf16 (hi only): [b][258][258][32]
#define P1W 258
#define NP1 ((size_t)BATCH * P1W * P1W * 32)
__device__ u16 g_p1[2][NP1];
// concat halo-padded channel-last bf16 (hi only): [b][130][130][128]
#define CCW 130
#define NCC ((size_t)BATCH * CCW * CCW * 128)
__device__ u16 g_cc[NCC];
__device__ float g_mean[BATCH * 128];

// pre-packed weights as uint4 {bhi0, bhi1, blo0, blo1}: [...][oc][sk][t]
__device__ uint4 g_wc1[64][2][4];
__device__ uint4 g_wc2[18][64][2][4];
__device__ uint4 g_wf[9][128][8][4];

// ------------------------- numeric helpers ---------------------------------
__device__ __forceinline__ u16 bf_hi(float v) {
    return __bfloat16_as_ushort(__float2bfloat16(v));
}
__device__ __forceinline__ u16 bf_lo(float v) {
    float h = __bfloat162float(__float2bfloat16(v));
    return __bfloat16_as_ushort(__float2bfloat16(v - h));
}
__device__ __forceinline__ uint32_t pack_hi2(float v0, float v1) {
    return (uint32_t)bf_hi(v0) | ((uint32_t)bf_hi(v1) << 16);
}
__device__ __forceinline__ uint32_t pack_lo2(float v0, float v1) {
    return (uint32_t)bf_lo(v0) | ((uint32_t)bf_lo(v1) << 16);
}

// m16n8k16 bf16 HMMA, D += A*B (fp32 accumulate)
__device__ __forceinline__ void mma16816(float* d, const uint32_t* a, uint32_t b0, uint32_t b1) {
    asm volatile(
        "mma.sync.aligned.m16n8k16.row.col.f32.bf16.bf16.f32 "
        "{%0,%1,%2,%3}, {%4,%5,%6,%7}, {%8,%9}, {%0,%1,%2,%3};"
        : "+f"(d[0]), "+f"(d[1]), "+f"(d[2]), "+f"(d[3])
        : "r"(a[0]), "r"(a[1]), "r"(a[2]), "r"(a[3]), "r"(b0), "r"(b1));
}

__device__ __forceinline__ uint32_t ld32(const u16* p) {
    return *(const uint32_t*)p;
}

// ------------------------- init kernels ------------------------------------
__global__ void zero_mean_kernel() {
    int i = threadIdx.x;
    if (i < BATCH * 128) g_mean[i] = 0.f;
}

// zero the halo ring of both pool1 planes. 1028 halo px/batch, 32 ch.
__global__ void halo_p1_kernel() {
    int idx = blockIdx.x * 256 + threadIdx.x;       // 8 b x 1028 px x 32 c
    if (idx >= BATCH * 1028 * 32) return;
    int c = idx & 31;
    int r = idx >> 5;
    int b = r / 1028;
    int p = r - b * 1028;
    int y, x;
    if (p < 258)      { y = 0;           x = p; }
    else if (p < 516) { y = 257;         x = p - 258; }
    else if (p < 772) { y = p - 516 + 1; x = 0; }
    else              { y = p - 772 + 1; x = 257; }
    size_t i = (((size_t)(b * P1W + y)) * P1W + x) * 32 + c;
    g_p1[0][i] = 0;
    g_p1[1][i] = 0;
}

// zero the halo ring of concat plane. 516 halo px/batch, 128 ch.
__global__ void halo_cc_kernel() {
    int idx = blockIdx.x * 256 + threadIdx.x;       // 8 b x 516 px x 128 c
    if (idx >= BATCH * 516 * 128) return;
    int c = idx & 127;
    int r = idx >> 7;
    int b = r / 516;
    int p = r - b * 516;
    int y, x;
    if (p < 130)      { y = 0;           x = p; }
    else if (p < 260) { y = 129;         x = p - 130; }
    else if (p < 388) { y = p - 260 + 1; x = 0; }
    else              { y = p - 388 + 1; x = 129; }
    g_cc[(((size_t)(b * CCW + y)) * CCW + x) * 128 + c] = 0;
}

// ------------------------- weight transforms -------------------------------
__device__ __forceinline__ float w1elem(const float* w, int ocl, int kk) {
    if (kk >= 27) return 0.f;
    int tap = kk / 3;
    int ic = kk - 3 * tap;
    return w[ocl * 27 + ic * 9 + tap];
}

__global__ void xform_w1(const float* __restrict__ wr, const float* __restrict__ wi) {
    int idx = blockIdx.x * 256 + threadIdx.x;       // 64 oc x 2 sk x 4 t
    if (idx >= 512) return;
    int oc = idx >> 3, sk = (idx >> 2) & 1, t = idx & 3;
    const float* w = (oc < 32) ? wr : wi;
    int ocl = oc & 31;
    int pA = t + 8 * sk, pB = pA + 4;
    float a0 = w1elem(w, ocl, 2 * pA), a1 = w1elem(w, ocl, 2 * pA + 1);
    float b0 = w1elem(w, ocl, 2 * pB), b1 = w1elem(w, ocl, 2 * pB + 1);
    g_wc1[oc][sk][t] = make_uint4(pack_hi2(a0, a1), pack_hi2(b0, b1),
                                  pack_lo2(a0, a1), pack_lo2(b0, b1));
}

__global__ void xform_w2(const float* __restrict__ w, int sidx) {
    int idx = blockIdx.x * 256 + threadIdx.x;       // 9 tap x 64 oc x 2 sk x 4 t
    if (idx >= 9 * 512) return;
    int tap = idx / 512;
    int rem = idx & 511;
    int oc = rem >> 3, sk = (rem >> 2) & 1, t = rem & 3;
    int pA = t + 8 * sk, pB = pA + 4;
    float a0 = w[oc * 288 + (2 * pA) * 9 + tap],     a1 = w[oc * 288 + (2 * pA + 1) * 9 + tap];
    float b0 = w[oc * 288 + (2 * pB) * 9 + tap],     b1 = w[oc * 288 + (2 * pB + 1) * 9 + tap];
    g_wc2[sidx * 9 + tap][oc][sk][t] = make_uint4(pack_hi2(a0, a1), pack_hi2(b0, b1),
                                                  pack_lo2(a0, a1), pack_lo2(b0, b1));
}

__global__ void xform_wf(const float* __restrict__ w) {
    int idx = blockIdx.x * 256 + threadIdx.x;       // 9 tap x 128 oc x 8 sk x 4 t
    if (idx >= 9 * 4096) return;
    int tap = idx >> 12;
    int rem = idx & 4095;
    int oc = rem >> 5, sk = (rem >> 2) & 7, t = rem & 3;
    int pA = t + 8 * sk, pB = pA + 4;
    float a0 = w[(oc * 128 + 2 * pA) * 9 + tap],     a1 = w[(oc * 128 + 2 * pA + 1) * 9 + tap];
    float b0 = w[(oc * 128 + 2 * pB) * 9 + tap],     b1 = w[(oc * 128 + 2 * pB + 1) * 9 + tap];
    g_wf[tap][oc][sk][t] = make_uint4(pack_hi2(a0, a1), pack_hi2(b0, b1),
                                      pack_lo2(a0, a1), pack_lo2(b0, b1));
}

// ======================= conv1 (both streams in one GEMM) ==================
__device__ __forceinline__ float conv1_fetch(const float* xb, int kk, int py, int px) {
    if (kk >= 27) return 0.f;
    int tap = kk / 3;
    int ic = kk - tap * 3;
    int kh = tap / 3;
    int kw = tap - kh * 3;
    int gy = py + kh - 1;
    int gx = px + kw - 1;
    if (gy < 0 || gy >= H0 || gx < 0 || gx >= H0) return 0.f;
    return xb[(size_t)ic * H0 * H0 + (size_t)gy * H0 + gx];
}

// grid 8192: (b, pooled row Y 0..255, x-group of 128 pre-pool cols).
// M=256 (2 dy frags x 128 xx), N=64, K=32 (27 used). A bf16-hi only.
__global__ void __launch_bounds__(256, 2)
conv1_mma(const float* __restrict__ x,
          const float* __restrict__ b_rgb,
          const float* __restrict__ b_ir) {
    __shared__ float s[128 * 65];
    int tid = threadIdx.x;
    int wid = tid >> 5;
    int lane = tid & 31;
    int g = lane >> 2;
    int t = lane & 3;
    int cbase = 2 * t;
    int bid = blockIdx.x;
    int x0 = (bid & 3) * 128;
    int Y = (bid >> 2) & 255;
    int b = bid >> 10;
    const float* xb = x + (size_t)b * 3 * H0 * H0;

    int xx0 = wid * 16 + g;
    int xx1 = xx0 + 8;

    float d[2][8][4];
#pragma unroll
    for (int f = 0; f < 2; f++)
#pragma unroll
        for (int nb = 0; nb < 8; nb++)
#pragma unroll
            for (int i = 0; i < 4; i++) d[f][nb][i] = 0.f;

#pragma unroll
    for (int sk = 0; sk < 2; sk++) {
        int k0 = sk * 16 + cbase;
        uint32_t aHi[2][4];
#pragma unroll
        for (int f = 0; f < 2; f++) {
            int py = 2 * Y + f;
            float v00 = conv1_fetch(xb, k0,     py, x0 + xx0);
            float v01 = conv1_fetch(xb, k0 + 1, py, x0 + xx0);
            float v08 = conv1_fetch(xb, k0 + 8, py, x0 + xx0);
            float v09 = conv1_fetch(xb, k0 + 9, py, x0 + xx0);
            float v10 = conv1_fetch(xb, k0,     py, x0 + xx1);
            float v11 = conv1_fetch(xb, k0 + 1, py, x0 + xx1);
            float v18 = conv1_fetch(xb, k0 + 8, py, x0 + xx1);
            float v19 = conv1_fetch(xb, k0 + 9, py, x0 + xx1);
            aHi[f][0] = pack_hi2(v00, v01);
            aHi[f][1] = pack_hi2(v10, v11);
            aHi[f][2] = pack_hi2(v08, v09);
            aHi[f][3] = pack_hi2(v18, v19);
        }
#pragma unroll
        for (int nb = 0; nb < 8; nb++) {
            int n = nb * 8 + g;
            uint4 w = g_wc1[n][sk][t];
#pragma unroll
            for (int f = 0; f < 2; f++) {
                mma16816(d[f][nb], aHi[f], w.x, w.y);
                mma16816(d[f][nb], aHi[f], w.z, w.w);
            }
        }
    }

    // 2-pass epilogue: pass f writes frag f rows (xx), pool across passes.
    float pm[16];
#pragma unroll
    for (int f = 0; f < 2; f++) {
#pragma unroll
        for (int nb = 0; nb < 8; nb++) {
            int c = nb * 8 + cbase;
            s[xx0 * 65 + c]     = d[f][nb][0];
            s[xx0 * 65 + c + 1] = d[f][nb][1];
            s[xx1 * 65 + c]     = d[f][nb][2];
            s[xx1 * 65 + c + 1] = d[f][nb][3];
        }
        __syncthreads();
#pragma unroll
        for (int k = 0; k < 16; k++) {
            int oi = k * 256 + tid;
            int oc = oi & 63;
            int j = oi >> 6;
            float m = fmaxf(s[(2 * j) * 65 + oc], s[(2 * j + 1) * 65 + oc]);
            if (f == 0) {
                pm[k] = m;
            } else {
                int st = oc >> 5;
                int ocl = oc & 31;
                float bi = st ? b_ir[ocl] : b_rgb[ocl];
                float v = fmaxf(fmaxf(pm[k], m) + bi, 0.f);
                size_t pix = (((size_t)(b * P1W + Y + 1)) * P1W + (x0 >> 1) + j + 1) * 32 + ocl;
                g_p1[st][pix] = bf_hi(v);
            }
        }
        __syncthreads();
    }
}

// ======================= conv2 (both streams, one launch) ==================
// grid 4096: (which, b, pooled row Y 0..127, x-group of 128 pre-pool cols).
// M=256 (2 dy frags x 128 xx), N=64 oc, K = 9 taps x 32 ic. Padded loads,
// fully unrolled taps. A bf16-hi only; B hi+lo from one uint4.
__global__ void __launch_bounds__(256, 2)
conv2_mma(const float* __restrict__ bias_r, const float* __restrict__ bias_i) {
    __shared__ float s[128 * 65];
    int tid = threadIdx.x;
    int wid = tid >> 5;
    int lane = tid & 31;
    int g = lane >> 2;
    int t = lane & 3;
    int cbase = 2 * t;
    int bid = blockIdx.x;
    int x0 = (bid & 1) * 128;
    int Y = (bid >> 1) & 127;
    int b = (bid >> 8) & 7;
    int which = bid >> 11;
    const u16* ph = g_p1[which];
    const float* bias = which ? bias_i : bias_r;
    int ch_off = which * 64;
    int wm0 = which * 9;

    int xx0 = wid * 16 + g;
    int xx1 = xx0 + 8;

    size_t pb[2][2];
#pragma unroll
    for (int f = 0; f < 2; f++) {
        pb[f][0] = (((size_t)(b * P1W + 2 * Y + f + 1)) * P1W + (x0 + xx0 + 1)) * 32;
        pb[f][1] = (((size_t)(b * P1W + 2 * Y + f + 1)) * P1W + (x0 + xx1 + 1)) * 32;
    }

    float d[2][8][4];
#pragma unroll
    for (int f = 0; f < 2; f++)
#pragma unroll
        for (int nb = 0; nb < 8; nb++)
#pragma unroll
            for (int i = 0; i < 4; i++) d[f][nb][i] = 0.f;

#pragma unroll
    for (int tap = 0; tap < 9; tap++) {
        const int kh = tap / 3;
        const int kw = tap - kh * 3;
        const ptrdiff_t to = ((ptrdiff_t)(kh - 1) * P1W + (kw - 1)) * 32;
        const uint4(*wt)[2][4] = g_wc2[wm0 + tap];
#pragma unroll
        for (int sk = 0; sk < 2; sk++) {
            int ic = sk * 16 + cbase;
            uint32_t aHi[2][4];
#pragma unroll
            for (int f = 0; f < 2; f++) {
                aHi[f][0] = ld32(ph + pb[f][0] + to + ic);
                aHi[f][1] = ld32(ph + pb[f][1] + to + ic);
                aHi[f][2] = ld32(ph + pb[f][0] + to + ic + 8);
                aHi[f][3] = ld32(ph + pb[f][1] + to + ic + 8);
            }
#pragma unroll
            for (int nb = 0; nb < 8; nb++) {
                int n = nb * 8 + g;
                uint4 w = wt[n][sk][t];
#pragma unroll
                for (int f = 0; f < 2; f++) {
                    mma16816(d[f][nb], aHi[f], w.x, w.y);
                    mma16816(d[f][nb], aHi[f], w.z, w.w);
                }
            }
        }
    }

    float pm[16];
#pragma unroll
    for (int f = 0; f < 2; f++) {
#pragma unroll
        for (int nb = 0; nb < 8; nb++) {
            int c = nb * 8 + cbase;
            s[xx0 * 65 + c]     = d[f][nb][0];
            s[xx0 * 65 + c + 1] = d[f][nb][1];
            s[xx1 * 65 + c]     = d[f][nb][2];
            s[xx1 * 65 + c + 1] = d[f][nb][3];
        }
        __syncthreads();
#pragma unroll
        for (int k = 0; k < 16; k++) {
            int oi = k * 256 + tid;
            int oc = oi & 63;
            int j = oi >> 6;
            float m = fmaxf(s[(2 * j) * 65 + oc], s[(2 * j + 1) * 65 + oc]);
            if (f == 0) {
                pm[k] = m;
            } else {
                float v = fmaxf(fmaxf(pm[k], m) + bias[oc], 0.f);
                size_t pix = (((size_t)(b * CCW + Y + 1)) * CCW + (x0 >> 1) + j + 1) * 128 + ch_off + oc;
                g_cc[pix] = bf_hi(v);
            }
        }
        __syncthreads();
    }
}

// ======================= fuse (128->128 conv + relu + mean) ================
// grid 1024: (b, y-pair 0..63, oc-half). M=256 (2 y rows x 128 x), N=64,
// K = 9 taps x 128 ic. Padded + unrolled. A bf16-hi only.
__global__ void __launch_bounds__(256, 2)
fuse_mma(const float* __restrict__ bias) {
    __shared__ float s[128 * 65];
    int tid = threadIdx.x;
    int wid = tid >> 5;
    int lane = tid & 31;
    int g = lane >> 2;
    int t = lane & 3;
    int cbase = 2 * t;
    int bid = blockIdx.x;
    int nh = bid & 1;
    int yp = (bid >> 1) & 63;
    int b = bid >> 7;
    int y0 = 2 * yp;

    int xx0 = wid * 16 + g;
    int xx1 = xx0 + 8;

    size_t pb[2][2];
#pragma unroll
    for (int f = 0; f < 2; f++) {
        pb[f][0] = (((size_t)(b * CCW + y0 + f + 1)) * CCW + (xx0 + 1)) * 128;
        pb[f][1] = (((size_t)(b * CCW + y0 + f + 1)) * CCW + (xx1 + 1)) * 128;
    }

    float d[2][8][4];
#pragma unroll
    for (int f = 0; f < 2; f++)
#pragma unroll
        for (int nb = 0; nb < 8; nb++)
#pragma unroll
            for (int i = 0; i < 4; i++) d[f][nb][i] = 0.f;

#pragma unroll
    for (int tap = 0; tap < 9; tap++) {
        const int kh = tap / 3;
        const int kw = tap - kh * 3;
        const ptrdiff_t to = ((ptrdiff_t)(kh - 1) * CCW + (kw - 1)) * 128;
        const uint4(*wt)[8][4] = g_wf[tap];
#pragma unroll
        for (int sk = 0; sk < 8; sk++) {
            int ic = sk * 16 + cbase;
            uint32_t aHi[2][4];
#pragma unroll
            for (int f = 0; f < 2; f++) {
                aHi[f][0] = ld32(g_cc + pb[f][0] + to + ic);
                aHi[f][1] = ld32(g_cc + pb[f][1] + to + ic);
                aHi[f][2] = ld32(g_cc + pb[f][0] + to + ic + 8);
                aHi[f][3] = ld32(g_cc + pb[f][1] + to + ic + 8);
            }
#pragma unroll
            for (int nb = 0; nb < 8; nb++) {
                int n = nh * 64 + nb * 8 + g;
                uint4 w = wt[n][sk][t];
#pragma unroll
                for (int f = 0; f < 2; f++) {
                    mma16816(d[f][nb], aHi[f], w.x, w.y);
                    mma16816(d[f][nb], aHi[f], w.z, w.w);
                }
            }
        }
    }

    // 2-pass epilogue: bias+relu into smem, column partial sums, atomic mean.
    int col = tid & 63;
    int q = tid >> 6;
    float csum = 0.f;
#pragma unroll
    for (int f = 0; f < 2; f++) {
#pragma unroll
        for (int nb = 0; nb < 8; nb++) {
            int c = nb * 8 + cbase;
            float b0 = bias[nh * 64 + c];
            float b1 = bias[nh * 64 + c + 1];
            s[xx0 * 65 + c]     = fmaxf(d[f][nb][0] + b0, 0.f);
            s[xx0 * 65 + c + 1] = fmaxf(d[f][nb][1] + b1, 0.f);
            s[xx1 * 65 + c]     = fmaxf(d[f][nb][2] + b0, 0.f);
            s[xx1 * 65 + c + 1] = fmaxf(d[f][nb][3] + b1, 0.f);
        }
        __syncthreads();
        for (int r = q * 32; r < q * 32 + 32; r++) csum += s[r * 65 + col];
        __syncthreads();
    }
    atomicAdd(&g_mean[b * 128 + nh * 64 + col], csum);
}

// ======================= head: det 1x1 + sigmoid + NMS =====================
__global__ void head_kernel(const float* __restrict__ det_w,
                            const float* __restrict__ det_b,
                            float* __restrict__ out) {
    int b = blockIdx.x;
    int lane = threadIdx.x;
    __shared__ float pv[18];
    if (lane < 18) {
        float acc = det_b[lane];
        for (int c = 0; c < 128; c++)
            acc = fmaf(det_w[lane * 128 + c], g_mean[b * 128 + c] * (1.f / 16384.f), acc);
        pv[lane] = acc;
    }
    __syncthreads();
    if (lane != 0) return;

    for (int i = 0; i < 18; i++) out[b * 18 + i] = pv[i];

    float bx[3][4], sc[3], eff[3];
    bool conf[3];
    for (int a = 0; a < 3; a++) {
        for (int k = 0; k < 4; k++) bx[a][k] = pv[a * 6 + k];
        sc[a] = 1.f / (1.f + expf(-pv[a * 6 + 4]));
        conf[a] = sc[a] > 0.5f;
        eff[a] = conf[a] ? sc[a] : -INFINITY;
    }
    int order[3];
    bool used[3] = {false, false, false};
    for (int i = 0; i < 3; i++) {
        int best = -1;
        for (int a = 0; a < 3; a++)
            if (!used[a] && (best < 0 || eff[a] > eff[best])) best = a;
        order[i] = best;
        used[best] = true;
    }
    float ox1[3], oy1[3], ox2[3], oy2[3], area[3];
    for (int i = 0; i < 3; i++) {
        int a = order[i];
        ox1[i] = bx[a][0]; oy1[i] = bx[a][1]; ox2[i] = bx[a][2]; oy2[i] = bx[a][3];
        area[i] = (ox2[i] - ox1[i]) * (oy2[i] - oy1[i]);
    }
    bool keep_s[3];
    bool sup[3] = {false, false, false};
    for (int i = 0; i < 3; i++) {
        bool valid = !sup[i];
        keep_s[i] = valid;
        if (valid) {
            for (int j = i + 1; j < 3; j++) {
                float ix1 = fmaxf(ox1[i], ox1[j]);
                float iy1 = fmaxf(oy1[i], oy1[j]);
                float ix2 = fminf(ox2[i], ox2[j]);
                float iy2 = fminf(oy2[i], oy2[j]);
                float inter = fmaxf(ix2 - ix1, 0.f) * fmaxf(iy2 - iy1, 0.f);
                float iou = inter / (area[i] + area[j] - inter);
                if (iou > 0.5f) sup[j] = true;
            }
        }
    }
    bool kp[3];
    for (int i = 0; i < 3; i++) kp[order[i]] = keep_s[i];
    for (int a = 0; a < 3; a++) kp[a] = kp[a] && conf[a];

    for (int a = 0; a < 3; a++) {
        for (int k = 0; k < 4; k++) out[144 + b * 12 + a * 4 + k] = bx[a][k];
        out[240 + b * 3 + a] = sc[a];
        out[264 + b * 3 + a] = kp[a] ? 1.f : 0.f;
    }
}

// ===========================================================================
extern "C" void kernel_launch(void* const* d_in, const int* in_sizes, int n_in,
                              void* d_out, int out_size) {
    const float* x      = (const float*)d_in[0];
    const float* rgb_w1 = (const float*)d_in[1];
    const float* rgb_b1 = (const float*)d_in[2];
    const float* rgb_w2 = (const float*)d_in[3];
    const float* rgb_b2 = (const float*)d_in[4];
    const float* ir_w1  = (const float*)d_in[5];
    const float* ir_b1  = (const float*)d_in[6];
    const float* ir_w2  = (const float*)d_in[7];
    const float* ir_b2  = (const float*)d_in[8];
    const float* fuse_w = (const float*)d_in[9];
    const float* fuse_b = (const float*)d_in[10];
    const float* det_w  = (const float*)d_in[11];
    const float* det_b  = (const float*)d_in[12];
    float* out = (float*)d_out;

    zero_mean_kernel<<<1, 1024>>>();
    halo_p1_kernel<<<(BATCH * 1028 * 32 + 255) / 256, 256>>>();
    halo_cc_kernel<<<(BATCH * 516 * 128 + 255) / 256, 256>>>();
    xform_w1<<<2, 256>>>(rgb_w1, ir_w1);
    xform_w2<<<18, 256>>>(rgb_w2, 0);
    xform_w2<<<18, 256>>>(ir_w2, 1);
    xform_wf<<<144, 256>>>(fuse_w);

    conv1_mma<<<8192, 256>>>(x, rgb_b1, ir_b1);
    conv2_mma<<<4096, 256>>>(rgb_b2, ir_b2);
    fuse_mma<<<1024, 256>>>(fuse_b);
    head_kernel<<<8, 32>>>(det_w, det_b, out);
}